// round 2
// baseline (speedup 1.0000x reference)
#include <cuda_runtime.h>
#include <cstdint>

#define NV   100000
#define ME   50000
#define PP   1600000
#define C    128
#define NEG_SLOPE 0.2f

// ---------------- scratch (device globals; no allocations allowed) ----------
__device__ float g_H[(size_t)NV * C];      // H = X W^T + b
__device__ float g_EdgeA[(size_t)ME * C];  // edge accumulators
__device__ float g_EdgeB[(size_t)ME * C];
__device__ float g_VertA[(size_t)NV * C];  // Hs accumulator
__device__ float g_VertB[(size_t)NV * C];  // Xv1 accumulator
__device__ float g_s[NV];
__device__ float g_d[NV];
__device__ float g_dv[NV];
__device__ float g_inv_dv[NV];
__device__ float g_dvi[NV];                // dv^-1/2
__device__ float g_de[ME];
__device__ float g_inv_de[ME];
__device__ float g_m[NV];                  // segment max of score per vertex
__device__ float g_ssum[NV];               // segment sum of exp per vertex
__device__ float g_score[PP];
__device__ float g_alpha[PP];

// ---------------- GEMM: H[i][j] = sum_k X[i][k]*W[j][k] + b[j] --------------
// BM=128, BN=128 (full C_OUT), BK=8, 256 threads, 8x8 per thread.
__global__ void gemm_kernel(const float* __restrict__ X,
                            const float* __restrict__ W,
                            const float* __restrict__ b,
                            float* __restrict__ H, int nrows) {
    __shared__ float As[8][128];
    __shared__ float Bs[8][128];
    const int tid  = threadIdx.x;
    const int row0 = blockIdx.x * 128;
    const int tx = tid % 16;          // col tile
    const int ty = tid / 16;          // row tile
    const int lr = tid / 2;           // load row within tile (0..127)
    const int lc = (tid % 2) * 4;     // load k-offset (0 or 4)

    float acc[8][8];
#pragma unroll
    for (int i = 0; i < 8; i++)
#pragma unroll
        for (int j = 0; j < 8; j++) acc[i][j] = 0.f;

    for (int k0 = 0; k0 < C; k0 += 8) {
        float4 xv = make_float4(0.f, 0.f, 0.f, 0.f);
        int gr = row0 + lr;
        if (gr < nrows) xv = *(const float4*)&X[(size_t)gr * C + k0 + lc];
        As[lc + 0][lr] = xv.x; As[lc + 1][lr] = xv.y;
        As[lc + 2][lr] = xv.z; As[lc + 3][lr] = xv.w;
        float4 wv = *(const float4*)&W[(size_t)lr * C + k0 + lc];
        Bs[lc + 0][lr] = wv.x; Bs[lc + 1][lr] = wv.y;
        Bs[lc + 2][lr] = wv.z; Bs[lc + 3][lr] = wv.w;
        __syncthreads();
#pragma unroll
        for (int k = 0; k < 8; k++) {
            float a[8], bb[8];
#pragma unroll
            for (int i = 0; i < 8; i++) a[i] = As[k][ty * 8 + i];
#pragma unroll
            for (int j = 0; j < 8; j++) bb[j] = Bs[k][tx * 8 + j];
#pragma unroll
            for (int i = 0; i < 8; i++)
#pragma unroll
                for (int j = 0; j < 8; j++) acc[i][j] = fmaf(a[i], bb[j], acc[i][j]);
        }
        __syncthreads();
    }
#pragma unroll
    for (int i = 0; i < 8; i++) {
        int r = row0 + ty * 8 + i;
        if (r < nrows) {
#pragma unroll
            for (int j = 0; j < 8; j++) {
                int c = tx * 8 + j;
                H[(size_t)r * C + c] = acc[i][j] + b[c];
            }
        }
    }
}

// ---------------- s = H w_src, d = H w_dst (warp per row) -------------------
__global__ void sd_kernel(const float* __restrict__ H,
                          const float* __restrict__ wsrc,
                          const float* __restrict__ wdst,
                          float* __restrict__ s, float* __restrict__ d) {
    int w = (blockIdx.x * blockDim.x + threadIdx.x) >> 5;
    int lane = threadIdx.x & 31;
    if (w >= NV) return;
    float4 h = *(const float4*)&H[(size_t)w * C + lane * 4];
    float4 a = *(const float4*)&wsrc[lane * 4];
    float4 bb = *(const float4*)&wdst[lane * 4];
    float ss = h.x * a.x + h.y * a.y + h.z * a.z + h.w * a.w;
    float dd = h.x * bb.x + h.y * bb.y + h.z * bb.z + h.w * bb.w;
#pragma unroll
    for (int o = 16; o; o >>= 1) {
        ss += __shfl_xor_sync(0xffffffffu, ss, o);
        dd += __shfl_xor_sync(0xffffffffu, dd, o);
    }
    if (lane == 0) { s[w] = ss; d[w] = dd; }
}

// ---------------- pair pass 1: degrees, score, segment max ------------------
__global__ void score_deg_kernel(const float* __restrict__ s,
                                 const float* __restrict__ d,
                                 const int* __restrict__ srcv,
                                 const int* __restrict__ pairv,
                                 const int* __restrict__ paire) {
    int p = blockIdx.x * blockDim.x + threadIdx.x;
    if (p >= PP) return;
    int v = pairv[p], e = paire[p], sv = srcv[p];
    float x = s[sv] + d[v];
    x = x > 0.f ? x : NEG_SLOPE * x;
    x = fminf(fmaxf(x, 0.001f), 5.0f);     // clip -> all positive
    g_score[p] = x;
    atomicMax((int*)&g_m[v], __float_as_int(x));   // valid: x > 0, m init 0
    atomicAdd(&g_dv[v], 1.f);
    atomicAdd(&g_de[e], 1.f);
}

// ---------------- vertex / edge degree finalize ------------------------------
__global__ void finalize_v_kernel() {
    int i = blockIdx.x * blockDim.x + threadIdx.x;
    if (i >= NV) return;
    float v = fmaxf(g_dv[i], 1.f);
    g_inv_dv[i] = 1.f / v;
    g_dvi[i] = 1.f / sqrtf(v);
}
__global__ void finalize_e_kernel() {
    int i = blockIdx.x * blockDim.x + threadIdx.x;
    if (i >= ME) return;
    g_inv_de[i] = 1.f / fmaxf(g_de[i], 1.f);
}

// ---------------- pair pass 2: sum of exp(score - m) per vertex -------------
__global__ void expsum_kernel(const int* __restrict__ pairv) {
    int p = blockIdx.x * blockDim.x + threadIdx.x;
    if (p >= PP) return;
    int v = pairv[p];
    atomicAdd(&g_ssum[v], __expf(g_score[p] - g_m[v]));
}

// ---------------- pair pass 3: alpha ----------------------------------------
__global__ void alpha_kernel(const int* __restrict__ pairv) {
    int p = blockIdx.x * blockDim.x + threadIdx.x;
    if (p >= PP) return;
    int v = pairv[p];
    g_alpha[p] = __expf(g_score[p] - g_m[v]) / g_ssum[v];
}

// ---------------- generic gather-scale-scatter (warp per pair) --------------
// dst[idst[p]] += src[isrc[p]] * (scale ? scale[isrc[p]] : 1) * (wp ? wp[p] : 1)
__global__ void scatter_kernel(const float* __restrict__ src,
                               float* __restrict__ dst,
                               const int* __restrict__ isrc,
                               const int* __restrict__ idst,
                               const float* __restrict__ scale,
                               const float* __restrict__ wp) {
    int gw = (blockIdx.x * blockDim.x + threadIdx.x) >> 5;
    if (gw >= PP) return;
    int lane = threadIdx.x & 31;
    int vs = __ldg(&isrc[gw]);
    int vd = __ldg(&idst[gw]);
    float mult = 1.f;
    if (scale) mult *= __ldg(&scale[vs]);
    if (wp)    mult *= __ldg(&wp[gw]);
    float4 x = *(const float4*)&src[(size_t)vs * C + lane * 4];
    float* dp = &dst[(size_t)vd * C + lane * 4];
    atomicAdd(dp + 0, x.x * mult);
    atomicAdd(dp + 1, x.y * mult);
    atomicAdd(dp + 2, x.z * mult);
    atomicAdd(dp + 3, x.w * mult);
}

// ---------------- output finalize: out = elu(acc * inv_dv) ------------------
__global__ void finalize_out_kernel(float* __restrict__ out) {
    int i = blockIdx.x * blockDim.x + threadIdx.x;
    if (i >= NV * C) return;
    float x = out[i] * g_inv_dv[i >> 7];
    out[i] = x > 0.f ? x : expm1f(x);
}

// ---------------- launch ------------------------------------------------------
extern "C" void kernel_launch(void* const* d_in, const int* in_sizes, int n_in,
                              void* d_out, int out_size) {
    const float* X      = (const float*)d_in[0];
    const int*   pair_v = (const int*)d_in[1];
    const int*   pair_e = (const int*)d_in[2];
    const int*   src_v  = (const int*)d_in[3];
    const float* Wt     = (const float*)d_in[4];
    const float* bt     = (const float*)d_in[5];
    const float* wsrc   = (const float*)d_in[6];
    const float* wdst   = (const float*)d_in[7];
    float* out = (float*)d_out;

    void *pH, *pEA, *pEB, *pVA, *pVB, *ps, *pd, *pdv, *pde, *pm, *pss;
    void *pdvi, *pinvde, *palpha;
    cudaGetSymbolAddress(&pH,  g_H);
    cudaGetSymbolAddress(&pEA, g_EdgeA);
    cudaGetSymbolAddress(&pEB, g_EdgeB);
    cudaGetSymbolAddress(&pVA, g_VertA);
    cudaGetSymbolAddress(&pVB, g_VertB);
    cudaGetSymbolAddress(&ps,  g_s);
    cudaGetSymbolAddress(&pd,  g_d);
    cudaGetSymbolAddress(&pdv, g_dv);
    cudaGetSymbolAddress(&pde, g_de);
    cudaGetSymbolAddress(&pm,  g_m);
    cudaGetSymbolAddress(&pss, g_ssum);
    cudaGetSymbolAddress(&pdvi,   g_dvi);
    cudaGetSymbolAddress(&pinvde, g_inv_de);
    cudaGetSymbolAddress(&palpha, g_alpha);

    const float* dvi    = (const float*)pdvi;
    const float* inv_de = (const float*)pinvde;
    const float* alpha  = (const float*)palpha;

    const int TB = 256;
    const int pairThreadBlocks = (PP + TB - 1) / TB;        // thread-per-pair
    const long long pw = (long long)PP * 32;
    const int pairWarpBlocks = (int)((pw + TB - 1) / TB);   // warp-per-pair
    const int gemmBlocks = (NV + 127) / 128;

    // 1) H = X W^T + b
    gemm_kernel<<<gemmBlocks, TB>>>(X, Wt, bt, (float*)pH, NV);
    // 2) s, d
    sd_kernel<<<(NV * 32 + TB - 1) / TB, TB>>>((const float*)pH, wsrc, wdst,
                                               (float*)ps, (float*)pd);
    // 3) zero accumulators for degree/softmax pass
    cudaMemsetAsync(pdv, 0, NV * sizeof(float));
    cudaMemsetAsync(pde, 0, ME * sizeof(float));
    cudaMemsetAsync(pm,  0, NV * sizeof(float));
    cudaMemsetAsync(pss, 0, NV * sizeof(float));
    // 4) score + degrees + segment max
    score_deg_kernel<<<pairThreadBlocks, TB>>>((const float*)ps, (const float*)pd,
                                               src_v, pair_v, pair_e);
    finalize_v_kernel<<<(NV + TB - 1) / TB, TB>>>();
    finalize_e_kernel<<<(ME + TB - 1) / TB, TB>>>();
    // 5) softmax denom + alpha
    expsum_kernel<<<pairThreadBlocks, TB>>>(pair_v);
    alpha_kernel<<<pairThreadBlocks, TB>>>(pair_v);

    // P1: EdgeA = segsum_e(H[v]*dvi[v])                  (= Xe * de)
    cudaMemsetAsync(pEA, 0, (size_t)ME * C * sizeof(float));
    scatter_kernel<<<pairWarpBlocks, TB>>>((const float*)pH, (float*)pEA,
                                           pair_v, pair_e, dvi, nullptr);
    // P2: VertA = segsum_v(EdgeA[e]*inv_de[e])           (= Hs / dvi)
    cudaMemsetAsync(pVA, 0, (size_t)NV * C * sizeof(float));
    scatter_kernel<<<pairWarpBlocks, TB>>>((const float*)pEA, (float*)pVA,
                                           pair_e, pair_v, inv_de, nullptr);
    // P3: EdgeB = segsum_e(VertA[v]*dvi[v])              (= Xe1 * de)
    cudaMemsetAsync(pEB, 0, (size_t)ME * C * sizeof(float));
    scatter_kernel<<<pairWarpBlocks, TB>>>((const float*)pVA, (float*)pEB,
                                           pair_v, pair_e, dvi, nullptr);
    // P4: VertB = segsum_v(alpha_p * EdgeB[e]*inv_de[e]) (= Xv1)
    cudaMemsetAsync(pVB, 0, (size_t)NV * C * sizeof(float));
    scatter_kernel<<<pairWarpBlocks, TB>>>((const float*)pEB, (float*)pVB,
                                           pair_e, pair_v, inv_de, alpha);
    // P5: EdgeA = segsum_e(VertB[v])                     (= Xe2 * de)
    cudaMemsetAsync(pEA, 0, (size_t)ME * C * sizeof(float));
    scatter_kernel<<<pairWarpBlocks, TB>>>((const float*)pVB, (float*)pEA,
                                           pair_v, pair_e, nullptr, nullptr);
    // P6: out = segsum_v(EdgeA[e]*inv_de[e])             (= Xv2 * dv)
    cudaMemsetAsync(out, 0, (size_t)NV * C * sizeof(float));
    scatter_kernel<<<pairWarpBlocks, TB>>>((const float*)pEA, out,
                                           pair_e, pair_v, inv_de, nullptr);
    // finalize: elu(out * inv_dv)
    finalize_out_kernel<<<(NV * C + TB - 1) / TB, TB>>>(out);
}

// round 3
// speedup vs baseline: 3.8995x; 3.8995x over previous
#include <cuda_runtime.h>
#include <cstdint>

#define NV   100000
#define ME   50000
#define PP   1600000
#define C    128
#define NEG_SLOPE 0.2f

// ---------------- scratch (device globals; no allocations allowed) ----------
__device__ float g_H[(size_t)NV * C];      // H = X W^T + b
__device__ float g_Edge[(size_t)ME * C];   // edge feature buffer (reused)
__device__ float g_Vert[(size_t)NV * C];   // vertex feature buffer (reused)
__device__ float g_s[NV];
__device__ float g_d[NV];
__device__ float g_inv_dv[NV];
__device__ float g_dvi[NV];                // dv^-1/2
__device__ float g_inv_de[ME];
__device__ float g_alpha[PP];              // per-slot (CSR_v order) softmax weight

__device__ int g_cnt_v[NV];
__device__ int g_cnt_e[ME];
__device__ int g_off_v[NV + 1];
__device__ int g_off_e[ME + 1];
__device__ int g_cur_v[NV];
__device__ int g_cur_e[ME];
__device__ int g_csr_v[PP];                // pair ids grouped by vertex
__device__ int g_csr_e[PP];                // pair ids grouped by edge

// ---------------- GEMM: H[i][j] = sum_k X[i][k]*W[j][k] + b[j] --------------
__global__ void gemm_kernel(const float* __restrict__ X,
                            const float* __restrict__ W,
                            const float* __restrict__ b,
                            float* __restrict__ H, int nrows) {
    __shared__ float As[8][128];
    __shared__ float Bs[8][128];
    const int tid  = threadIdx.x;
    const int row0 = blockIdx.x * 128;
    const int tx = tid % 16;
    const int ty = tid / 16;
    const int lr = tid / 2;
    const int lc = (tid % 2) * 4;

    float acc[8][8];
#pragma unroll
    for (int i = 0; i < 8; i++)
#pragma unroll
        for (int j = 0; j < 8; j++) acc[i][j] = 0.f;

    for (int k0 = 0; k0 < C; k0 += 8) {
        float4 xv = make_float4(0.f, 0.f, 0.f, 0.f);
        int gr = row0 + lr;
        if (gr < nrows) xv = *(const float4*)&X[(size_t)gr * C + k0 + lc];
        As[lc + 0][lr] = xv.x; As[lc + 1][lr] = xv.y;
        As[lc + 2][lr] = xv.z; As[lc + 3][lr] = xv.w;
        float4 wv = *(const float4*)&W[(size_t)lr * C + k0 + lc];
        Bs[lc + 0][lr] = wv.x; Bs[lc + 1][lr] = wv.y;
        Bs[lc + 2][lr] = wv.z; Bs[lc + 3][lr] = wv.w;
        __syncthreads();
#pragma unroll
        for (int k = 0; k < 8; k++) {
            float a[8], bb[8];
#pragma unroll
            for (int i = 0; i < 8; i++) a[i] = As[k][ty * 8 + i];
#pragma unroll
            for (int j = 0; j < 8; j++) bb[j] = Bs[k][tx * 8 + j];
#pragma unroll
            for (int i = 0; i < 8; i++)
#pragma unroll
                for (int j = 0; j < 8; j++) acc[i][j] = fmaf(a[i], bb[j], acc[i][j]);
        }
        __syncthreads();
    }
#pragma unroll
    for (int i = 0; i < 8; i++) {
        int r = row0 + ty * 8 + i;
        if (r < nrows) {
#pragma unroll
            for (int j = 0; j < 8; j++) {
                int c = tx * 8 + j;
                H[(size_t)r * C + c] = acc[i][j] + b[c];
            }
        }
    }
}

// ---------------- s = H w_src, d = H w_dst (warp per row) -------------------
__global__ void sd_kernel(const float* __restrict__ H,
                          const float* __restrict__ wsrc,
                          const float* __restrict__ wdst,
                          float* __restrict__ s, float* __restrict__ d) {
    int w = (blockIdx.x * blockDim.x + threadIdx.x) >> 5;
    int lane = threadIdx.x & 31;
    if (w >= NV) return;
    float4 h = *(const float4*)&H[(size_t)w * C + lane * 4];
    float4 a = *(const float4*)&wsrc[lane * 4];
    float4 bb = *(const float4*)&wdst[lane * 4];
    float ss = h.x * a.x + h.y * a.y + h.z * a.z + h.w * a.w;
    float dd = h.x * bb.x + h.y * bb.y + h.z * bb.z + h.w * bb.w;
#pragma unroll
    for (int o = 16; o; o >>= 1) {
        ss += __shfl_xor_sync(0xffffffffu, ss, o);
        dd += __shfl_xor_sync(0xffffffffu, dd, o);
    }
    if (lane == 0) { s[w] = ss; d[w] = dd; }
}

// ---------------- CSR build: histogram -------------------------------------
__global__ void hist_kernel(const int* __restrict__ pv, const int* __restrict__ pe) {
    int p = blockIdx.x * blockDim.x + threadIdx.x;
    if (p >= PP) return;
    atomicAdd(&g_cnt_v[pv[p]], 1);
    atomicAdd(&g_cnt_e[pe[p]], 1);
}

// ---------------- single-block exclusive scan (shuffle-based) ---------------
__global__ void exscan_kernel(const int* __restrict__ in, int* __restrict__ out, int n) {
    __shared__ int warp_sums[32];
    __shared__ int s_carry;
    const int tid = threadIdx.x, lane = tid & 31, wid = tid >> 5;
    const int nw = blockDim.x >> 5;
    if (tid == 0) s_carry = 0;
    __syncthreads();
    for (int base = 0; base < n; base += blockDim.x) {
        int i = base + tid;
        int v = (i < n) ? in[i] : 0;
        int x = v;
#pragma unroll
        for (int o = 1; o < 32; o <<= 1) {
            int t = __shfl_up_sync(0xffffffffu, x, o);
            if (lane >= o) x += t;
        }
        if (lane == 31) warp_sums[wid] = x;
        __syncthreads();
        if (wid == 0) {
            int ws = (lane < nw) ? warp_sums[lane] : 0;
#pragma unroll
            for (int o = 1; o < 32; o <<= 1) {
                int t = __shfl_up_sync(0xffffffffu, ws, o);
                if (lane >= o) ws += t;
            }
            warp_sums[lane] = ws;   // inclusive warp-sum scan
        }
        __syncthreads();
        int warp_off = (wid == 0) ? 0 : warp_sums[wid - 1];
        int carry = s_carry;
        if (i < n) out[i] = carry + warp_off + x - v;
        __syncthreads();
        if (tid == blockDim.x - 1) s_carry = carry + warp_off + x;
        __syncthreads();
    }
    if (tid == 0) out[n] = s_carry;
}

// ---------------- CSR fill ---------------------------------------------------
__global__ void fill_kernel(const int* __restrict__ pv, const int* __restrict__ pe) {
    int p = blockIdx.x * blockDim.x + threadIdx.x;
    if (p >= PP) return;
    g_csr_v[atomicAdd(&g_cur_v[pv[p]], 1)] = p;
    g_csr_e[atomicAdd(&g_cur_e[pe[p]], 1)] = p;
}

// ---------------- degree finalize -------------------------------------------
__global__ void finalize_v_kernel() {
    int i = blockIdx.x * blockDim.x + threadIdx.x;
    if (i >= NV) return;
    float v = (float)max(g_cnt_v[i], 1);
    g_inv_dv[i] = 1.f / v;
    g_dvi[i] = rsqrtf(v);
}
__global__ void finalize_e_kernel() {
    int i = blockIdx.x * blockDim.x + threadIdx.x;
    if (i >= ME) return;
    g_inv_de[i] = 1.f / (float)max(g_cnt_e[i], 1);
}

// ---------------- softmax: warp per vertex over CSR_v -----------------------
__device__ __forceinline__ float pair_score(const float* s, const int* srcv,
                                            int p, float dval) {
    float x = __ldg(&s[__ldg(&srcv[p])]) + dval;
    x = x > 0.f ? x : NEG_SLOPE * x;
    return fminf(fmaxf(x, 0.001f), 5.0f);
}

__global__ void softmax_kernel(const float* __restrict__ s,
                               const float* __restrict__ d,
                               const int* __restrict__ srcv) {
    int v = blockIdx.x * (blockDim.x >> 5) + (threadIdx.x >> 5);
    if (v >= NV) return;
    int lane = threadIdx.x & 31;
    int beg = g_off_v[v], end = g_off_v[v + 1];
    if (beg == end) return;
    float dval = __ldg(&d[v]);
    float mx = -1e30f;
    for (int i = beg + lane; i < end; i += 32)
        mx = fmaxf(mx, pair_score(s, srcv, g_csr_v[i], dval));
#pragma unroll
    for (int o = 16; o; o >>= 1) mx = fmaxf(mx, __shfl_xor_sync(0xffffffffu, mx, o));
    float sum = 0.f;
    for (int i = beg + lane; i < end; i += 32)
        sum += __expf(pair_score(s, srcv, g_csr_v[i], dval) - mx);
#pragma unroll
    for (int o = 16; o; o >>= 1) sum += __shfl_xor_sync(0xffffffffu, sum, o);
    float inv = 1.f / sum;
    for (int i = beg + lane; i < end; i += 32)
        g_alpha[i] = __expf(pair_score(s, srcv, g_csr_v[i], dval) - mx) * inv;
}

// ---------------- CSR gather segment-sum (warp per output row) --------------
// dst[row] = oscale[row] * sum_{i in [off[row],off[row+1])}
//              src[oidx[csr[i]]] * (SRC_SCALE? sscale[oidx] :1) * (PAIRW? pw[i] :1)
template<bool SRC_SCALE, bool PAIRW, bool ELU>
__global__ void gather_kernel(const float* __restrict__ src,
                              float* __restrict__ dst,
                              const int* __restrict__ csr,
                              const int* __restrict__ off,
                              const int* __restrict__ oidx,
                              const float* __restrict__ sscale,
                              const float* __restrict__ pw,
                              const float* __restrict__ oscale,
                              int nrows) {
    int row = blockIdx.x * (blockDim.x >> 5) + (threadIdx.x >> 5);
    if (row >= nrows) return;
    int lane = threadIdx.x & 31;
    int beg = __ldg(&off[row]), end = __ldg(&off[row + 1]);
    float ax = 0.f, ay = 0.f, az = 0.f, aw = 0.f;
    int i = beg;
    for (; i + 4 <= end; i += 4) {
        int p[4], sI[4]; float w[4];
#pragma unroll
        for (int u = 0; u < 4; u++) p[u] = __ldg(&csr[i + u]);
#pragma unroll
        for (int u = 0; u < 4; u++) sI[u] = __ldg(&oidx[p[u]]);
#pragma unroll
        for (int u = 0; u < 4; u++) {
            w[u] = 1.f;
            if (SRC_SCALE) w[u] *= __ldg(&sscale[sI[u]]);
            if (PAIRW)     w[u] *= __ldg(&pw[i + u]);
        }
#pragma unroll
        for (int u = 0; u < 4; u++) {
            float4 x = *(const float4*)&src[(size_t)sI[u] * C + lane * 4];
            ax = fmaf(w[u], x.x, ax); ay = fmaf(w[u], x.y, ay);
            az = fmaf(w[u], x.z, az); aw = fmaf(w[u], x.w, aw);
        }
    }
    for (; i < end; i++) {
        int p = __ldg(&csr[i]);
        int sI = __ldg(&oidx[p]);
        float w = 1.f;
        if (SRC_SCALE) w *= __ldg(&sscale[sI]);
        if (PAIRW)     w *= __ldg(&pw[i]);
        float4 x = *(const float4*)&src[(size_t)sI * C + lane * 4];
        ax = fmaf(w, x.x, ax); ay = fmaf(w, x.y, ay);
        az = fmaf(w, x.z, az); aw = fmaf(w, x.w, aw);
    }
    float os = oscale ? __ldg(&oscale[row]) : 1.f;
    ax *= os; ay *= os; az *= os; aw *= os;
    if (ELU) {
        ax = ax > 0.f ? ax : expm1f(ax);
        ay = ay > 0.f ? ay : expm1f(ay);
        az = az > 0.f ? az : expm1f(az);
        aw = aw > 0.f ? aw : expm1f(aw);
    }
    *(float4*)&dst[(size_t)row * C + lane * 4] = make_float4(ax, ay, az, aw);
}

// ---------------- launch ------------------------------------------------------
extern "C" void kernel_launch(void* const* d_in, const int* in_sizes, int n_in,
                              void* d_out, int out_size) {
    const float* X      = (const float*)d_in[0];
    const int*   pair_v = (const int*)d_in[1];
    const int*   pair_e = (const int*)d_in[2];
    const int*   src_v  = (const int*)d_in[3];
    const float* Wt     = (const float*)d_in[4];
    const float* bt     = (const float*)d_in[5];
    const float* wsrc   = (const float*)d_in[6];
    const float* wdst   = (const float*)d_in[7];
    float* out = (float*)d_out;

    void *pH, *pE, *pV, *ps, *pd, *pcv, *pce, *pov, *poe, *pcurv, *pcure;
    void *pdvi, *pinvde, *pinvdv, *palpha, *pcsrv, *pcsre;
    cudaGetSymbolAddress(&pH,  g_H);
    cudaGetSymbolAddress(&pE,  g_Edge);
    cudaGetSymbolAddress(&pV,  g_Vert);
    cudaGetSymbolAddress(&ps,  g_s);
    cudaGetSymbolAddress(&pd,  g_d);
    cudaGetSymbolAddress(&pcv, g_cnt_v);
    cudaGetSymbolAddress(&pce, g_cnt_e);
    cudaGetSymbolAddress(&pov, g_off_v);
    cudaGetSymbolAddress(&poe, g_off_e);
    cudaGetSymbolAddress(&pcurv, g_cur_v);
    cudaGetSymbolAddress(&pcure, g_cur_e);
    cudaGetSymbolAddress(&pdvi,   g_dvi);
    cudaGetSymbolAddress(&pinvde, g_inv_de);
    cudaGetSymbolAddress(&pinvdv, g_inv_dv);
    cudaGetSymbolAddress(&palpha, g_alpha);
    cudaGetSymbolAddress(&pcsrv,  g_csr_v);
    cudaGetSymbolAddress(&pcsre,  g_csr_e);

    const float* H      = (const float*)pH;
    float*       Ebuf   = (float*)pE;
    float*       Vbuf   = (float*)pV;
    const float* dvi    = (const float*)pdvi;
    const float* inv_de = (const float*)pinvde;
    const float* inv_dv = (const float*)pinvdv;
    const float* alpha  = (const float*)palpha;
    const int*   csr_v  = (const int*)pcsrv;
    const int*   csr_e  = (const int*)pcsre;
    const int*   off_v  = (const int*)pov;
    const int*   off_e  = (const int*)poe;

    const int TB = 256;
    const int WPB = TB / 32;                      // warps (rows) per block
    const int pairBlocks = (PP + TB - 1) / TB;
    const int gemmBlocks = (NV + 127) / 128;
    const int eRowBlocks = (ME + WPB - 1) / WPB;
    const int vRowBlocks = (NV + WPB - 1) / WPB;

    // 1) H = X W^T + b
    gemm_kernel<<<gemmBlocks, TB>>>(X, Wt, bt, (float*)pH, NV);
    // 2) s, d
    sd_kernel<<<(NV * 32 + TB - 1) / TB, TB>>>(H, wsrc, wdst, (float*)ps, (float*)pd);

    // 3) CSR build
    cudaMemsetAsync(pcv, 0, NV * sizeof(int));
    cudaMemsetAsync(pce, 0, ME * sizeof(int));
    hist_kernel<<<pairBlocks, TB>>>(pair_v, pair_e);
    exscan_kernel<<<1, 1024>>>((const int*)pcv, (int*)pov, NV);
    exscan_kernel<<<1, 1024>>>((const int*)pce, (int*)poe, ME);
    cudaMemcpyAsync(pcurv, pov, NV * sizeof(int), cudaMemcpyDeviceToDevice);
    cudaMemcpyAsync(pcure, poe, ME * sizeof(int), cudaMemcpyDeviceToDevice);
    fill_kernel<<<pairBlocks, TB>>>(pair_v, pair_e);
    finalize_v_kernel<<<(NV + TB - 1) / TB, TB>>>();
    finalize_e_kernel<<<(ME + TB - 1) / TB, TB>>>();

    // 4) softmax alpha (per CSR_v slot)
    softmax_kernel<<<vRowBlocks, TB>>>((const float*)ps, (const float*)pd, src_v);

    // 5) feature passes (all gather, no atomics)
    // P1: Edge = Xe = inv_de * segsum_e( H[v] * dvi[v] )
    gather_kernel<true, false, false><<<eRowBlocks, TB>>>(
        H, Ebuf, csr_e, off_e, pair_v, dvi, nullptr, inv_de, ME);
    // P2: Vert = Hs = dvi[v] * segsum_v( Edge[e] )
    gather_kernel<false, false, false><<<vRowBlocks, TB>>>(
        Ebuf, Vbuf, csr_v, off_v, pair_e, nullptr, nullptr, dvi, NV);
    // P3: Edge = Xe1 = inv_de * segsum_e( Vert[v] )
    gather_kernel<false, false, false><<<eRowBlocks, TB>>>(
        Vbuf, Ebuf, csr_e, off_e, pair_v, nullptr, nullptr, inv_de, ME);
    // P4: Vert = Xv1 = segsum_v( alpha_slot * Edge[e] )
    gather_kernel<false, true, false><<<vRowBlocks, TB>>>(
        Ebuf, Vbuf, csr_v, off_v, pair_e, nullptr, alpha, nullptr, NV);
    // P5: Edge = Xe2 = inv_de * segsum_e( Vert[v] )
    gather_kernel<false, false, false><<<eRowBlocks, TB>>>(
        Vbuf, Ebuf, csr_e, off_e, pair_v, nullptr, nullptr, inv_de, ME);
    // P6: out = elu( inv_dv * segsum_v( Edge[e] ) )
    gather_kernel<false, false, true><<<vRowBlocks, TB>>>(
        Ebuf, out, csr_v, off_v, pair_e, nullptr, nullptr, inv_dv, NV);
}

// round 4
// speedup vs baseline: 4.9368x; 1.2660x over previous
#include <cuda_runtime.h>
#include <cstdint>

#define NV   100000
#define ME   50000
#define PP   1600000
#define C    128
#define NEG_SLOPE 0.2f
#define SCAN_B 1024

// ---------------- scratch (device globals; no allocations allowed) ----------
__device__ float g_H[(size_t)NV * C];      // H = X W^T + b
__device__ float g_Edge[(size_t)ME * C];   // edge feature buffer (reused)
__device__ float g_Vert[(size_t)NV * C];   // vertex feature buffer (reused)
__device__ float g_s[NV];
__device__ float g_d[NV];
__device__ float g_inv_dv[NV];
__device__ float g_dvi[NV];                // dv^-1/2
__device__ float g_inv_de[ME];
__device__ float g_alpha[PP];              // per-slot (CSR_v order) softmax weight

__device__ int g_cnt_v[NV];
__device__ int g_cnt_e[ME];
__device__ int g_off_v[NV + 1];
__device__ int g_off_e[ME + 1];
__device__ int g_cur_v[NV];
__device__ int g_cur_e[ME];
__device__ int g_csr_v_src[PP];            // edge id per vertex-grouped slot
__device__ int g_csr_v_sv[PP];             // src_v per vertex-grouped slot
__device__ int g_csr_e_src[PP];            // vertex id per edge-grouped slot
__device__ int g_part_v[256];              // scan partials
__device__ int g_part_e[256];

// ---------------- GEMM: H[i][j] = sum_k X[i][k]*W[j][k] + b[j] --------------
__global__ void gemm_kernel(const float* __restrict__ X,
                            const float* __restrict__ W,
                            const float* __restrict__ b,
                            float* __restrict__ H, int nrows) {
    __shared__ float As[8][128];
    __shared__ float Bs[8][128];
    const int tid  = threadIdx.x;
    const int row0 = blockIdx.x * 128;
    const int tx = tid % 16;
    const int ty = tid / 16;
    const int lr = tid / 2;
    const int lc = (tid % 2) * 4;

    float acc[8][8];
#pragma unroll
    for (int i = 0; i < 8; i++)
#pragma unroll
        for (int j = 0; j < 8; j++) acc[i][j] = 0.f;

    for (int k0 = 0; k0 < C; k0 += 8) {
        float4 xv = make_float4(0.f, 0.f, 0.f, 0.f);
        int gr = row0 + lr;
        if (gr < nrows) xv = *(const float4*)&X[(size_t)gr * C + k0 + lc];
        As[lc + 0][lr] = xv.x; As[lc + 1][lr] = xv.y;
        As[lc + 2][lr] = xv.z; As[lc + 3][lr] = xv.w;
        float4 wv = *(const float4*)&W[(size_t)lr * C + k0 + lc];
        Bs[lc + 0][lr] = wv.x; Bs[lc + 1][lr] = wv.y;
        Bs[lc + 2][lr] = wv.z; Bs[lc + 3][lr] = wv.w;
        __syncthreads();
#pragma unroll
        for (int k = 0; k < 8; k++) {
            float a[8], bb[8];
#pragma unroll
            for (int i = 0; i < 8; i++) a[i] = As[k][ty * 8 + i];
#pragma unroll
            for (int j = 0; j < 8; j++) bb[j] = Bs[k][tx * 8 + j];
#pragma unroll
            for (int i = 0; i < 8; i++)
#pragma unroll
                for (int j = 0; j < 8; j++) acc[i][j] = fmaf(a[i], bb[j], acc[i][j]);
        }
        __syncthreads();
    }
#pragma unroll
    for (int i = 0; i < 8; i++) {
        int r = row0 + ty * 8 + i;
        if (r < nrows) {
#pragma unroll
            for (int j = 0; j < 8; j++) {
                int c = tx * 8 + j;
                H[(size_t)r * C + c] = acc[i][j] + b[c];
            }
        }
    }
}

// ---------------- s = H w_src, d = H w_dst (warp per row) -------------------
__global__ void sd_kernel(const float* __restrict__ H,
                          const float* __restrict__ wsrc,
                          const float* __restrict__ wdst,
                          float* __restrict__ s, float* __restrict__ d) {
    int w = (blockIdx.x * blockDim.x + threadIdx.x) >> 5;
    int lane = threadIdx.x & 31;
    if (w >= NV) return;
    float4 h = *(const float4*)&H[(size_t)w * C + lane * 4];
    float4 a = *(const float4*)&wsrc[lane * 4];
    float4 bb = *(const float4*)&wdst[lane * 4];
    float ss = h.x * a.x + h.y * a.y + h.z * a.z + h.w * a.w;
    float dd = h.x * bb.x + h.y * bb.y + h.z * bb.z + h.w * bb.w;
#pragma unroll
    for (int o = 16; o; o >>= 1) {
        ss += __shfl_xor_sync(0xffffffffu, ss, o);
        dd += __shfl_xor_sync(0xffffffffu, dd, o);
    }
    if (lane == 0) { s[w] = ss; d[w] = dd; }
}

// ---------------- CSR build: histogram -------------------------------------
__global__ void hist_kernel(const int* __restrict__ pv, const int* __restrict__ pe) {
    int p = blockIdx.x * blockDim.x + threadIdx.x;
    if (p >= PP) return;
    atomicAdd(&g_cnt_v[pv[p]], 1);
    atomicAdd(&g_cnt_e[pe[p]], 1);
}

// ---------------- 3-phase exclusive scan ------------------------------------
// phase 1: per-block sums
__global__ void scan_reduce_kernel(const int* __restrict__ in, int* __restrict__ part, int n) {
    __shared__ int wsum[32];
    int i = blockIdx.x * SCAN_B + threadIdx.x;
    int v = (i < n) ? in[i] : 0;
    int lane = threadIdx.x & 31, wid = threadIdx.x >> 5;
#pragma unroll
    for (int o = 16; o; o >>= 1) v += __shfl_xor_sync(0xffffffffu, v, o);
    if (lane == 0) wsum[wid] = v;
    __syncthreads();
    if (wid == 0) {
        int x = (lane < (SCAN_B >> 5)) ? wsum[lane] : 0;
#pragma unroll
        for (int o = 16; o; o >>= 1) x += __shfl_xor_sync(0xffffffffu, x, o);
        if (lane == 0) part[blockIdx.x] = x;
    }
}
// phase 2: single-block exclusive scan of partials (nb <= 1024)
__global__ void scan_partials_kernel(int* __restrict__ part, int nb) {
    __shared__ int wsum[32];
    int tid = threadIdx.x, lane = tid & 31, wid = tid >> 5;
    int v = (tid < nb) ? part[tid] : 0;
    int x = v;
#pragma unroll
    for (int o = 1; o < 32; o <<= 1) {
        int t = __shfl_up_sync(0xffffffffu, x, o);
        if (lane >= o) x += t;
    }
    if (lane == 31) wsum[wid] = x;
    __syncthreads();
    if (wid == 0) {
        int w = (lane < 32) ? wsum[lane] : 0;
#pragma unroll
        for (int o = 1; o < 32; o <<= 1) {
            int t = __shfl_up_sync(0xffffffffu, w, o);
            if (lane >= o) w += t;
        }
        wsum[lane] = w;
    }
    __syncthreads();
    int off = (wid == 0) ? 0 : wsum[wid - 1];
    if (tid < nb) part[tid] = off + x - v;     // exclusive
}
// phase 3: per-block exclusive scan + carry; writes off and cur; off[n] = PP
__global__ void scan_apply_kernel(const int* __restrict__ in,
                                  const int* __restrict__ part,
                                  int* __restrict__ off, int* __restrict__ cur, int n) {
    __shared__ int wsum[32];
    int i = blockIdx.x * SCAN_B + threadIdx.x;
    int lane = threadIdx.x & 31, wid = threadIdx.x >> 5;
    int v = (i < n) ? in[i] : 0;
    int x = v;
#pragma unroll
    for (int o = 1; o < 32; o <<= 1) {
        int t = __shfl_up_sync(0xffffffffu, x, o);
        if (lane >= o) x += t;
    }
    if (lane == 31) wsum[wid] = x;
    __syncthreads();
    if (wid == 0) {
        int w = (lane < (SCAN_B >> 5)) ? wsum[lane] : 0;
#pragma unroll
        for (int o = 1; o < 32; o <<= 1) {
            int t = __shfl_up_sync(0xffffffffu, w, o);
            if (lane >= o) w += t;
        }
        wsum[lane] = w;
    }
    __syncthreads();
    int woff = (wid == 0) ? 0 : wsum[wid - 1];
    if (i < n) {
        int val = part[blockIdx.x] + woff + x - v;
        off[i] = val;
        cur[i] = val;
    }
    if (i == 0) off[n] = PP;   // total count is statically PP
}

// ---------------- CSR fill (direct source indices) ---------------------------
__global__ void fill_kernel(const int* __restrict__ pv, const int* __restrict__ pe,
                            const int* __restrict__ sv) {
    int p = blockIdx.x * blockDim.x + threadIdx.x;
    if (p >= PP) return;
    int v = pv[p], e = pe[p];
    int slot_v = atomicAdd(&g_cur_v[v], 1);
    g_csr_v_src[slot_v] = e;
    g_csr_v_sv[slot_v]  = sv[p];
    int slot_e = atomicAdd(&g_cur_e[e], 1);
    g_csr_e_src[slot_e] = v;
}

// ---------------- degree finalize -------------------------------------------
__global__ void finalize_v_kernel() {
    int i = blockIdx.x * blockDim.x + threadIdx.x;
    if (i >= NV) return;
    float v = (float)max(g_cnt_v[i], 1);
    g_inv_dv[i] = 1.f / v;
    g_dvi[i] = rsqrtf(v);
}
__global__ void finalize_e_kernel() {
    int i = blockIdx.x * blockDim.x + threadIdx.x;
    if (i >= ME) return;
    g_inv_de[i] = 1.f / (float)max(g_cnt_e[i], 1);
}

// ---------------- softmax: warp per vertex over CSR_v -----------------------
__device__ __forceinline__ float slot_score(const float* s, int i, float dval) {
    float x = __ldg(&s[g_csr_v_sv[i]]) + dval;
    x = x > 0.f ? x : NEG_SLOPE * x;
    return fminf(fmaxf(x, 0.001f), 5.0f);
}

__global__ void softmax_kernel(const float* __restrict__ s,
                               const float* __restrict__ d) {
    int v = blockIdx.x * (blockDim.x >> 5) + (threadIdx.x >> 5);
    if (v >= NV) return;
    int lane = threadIdx.x & 31;
    int beg = g_off_v[v], end = g_off_v[v + 1];
    if (beg == end) return;
    float dval = __ldg(&d[v]);
    float mx = -1e30f;
    for (int i = beg + lane; i < end; i += 32)
        mx = fmaxf(mx, slot_score(s, i, dval));
#pragma unroll
    for (int o = 16; o; o >>= 1) mx = fmaxf(mx, __shfl_xor_sync(0xffffffffu, mx, o));
    float sum = 0.f;
    for (int i = beg + lane; i < end; i += 32)
        sum += __expf(slot_score(s, i, dval) - mx);
#pragma unroll
    for (int o = 16; o; o >>= 1) sum += __shfl_xor_sync(0xffffffffu, sum, o);
    float inv = 1.f / sum;
    for (int i = beg + lane; i < end; i += 32)
        g_alpha[i] = __expf(slot_score(s, i, dval) - mx) * inv;
}

// ---------------- CSR gather segment-sum (warp per output row) --------------
// dst[row] = oscale[row] * sum_i src[csr[i]] * (SRC_SCALE? sscale[csr[i]] :1)
//                                            * (PAIRW? pw[i] :1)
template<bool SRC_SCALE, bool PAIRW, bool ELU>
__global__ void gather_kernel(const float* __restrict__ src,
                              float* __restrict__ dst,
                              const int* __restrict__ csr,
                              const int* __restrict__ off,
                              const float* __restrict__ sscale,
                              const float* __restrict__ pw,
                              const float* __restrict__ oscale,
                              int nrows) {
    int row = blockIdx.x * (blockDim.x >> 5) + (threadIdx.x >> 5);
    if (row >= nrows) return;
    int lane = threadIdx.x & 31;
    int beg = __ldg(&off[row]), end = __ldg(&off[row + 1]);
    float ax = 0.f, ay = 0.f, az = 0.f, aw = 0.f;
    int i = beg;
    for (; i + 4 <= end; i += 4) {
        int sI[4]; float w[4];
#pragma unroll
        for (int u = 0; u < 4; u++) sI[u] = __ldg(&csr[i + u]);
#pragma unroll
        for (int u = 0; u < 4; u++) {
            w[u] = 1.f;
            if (SRC_SCALE) w[u] *= __ldg(&sscale[sI[u]]);
            if (PAIRW)     w[u] *= __ldg(&pw[i + u]);
        }
#pragma unroll
        for (int u = 0; u < 4; u++) {
            float4 x = *(const float4*)&src[(size_t)sI[u] * C + lane * 4];
            ax = fmaf(w[u], x.x, ax); ay = fmaf(w[u], x.y, ay);
            az = fmaf(w[u], x.z, az); aw = fmaf(w[u], x.w, aw);
        }
    }
    for (; i < end; i++) {
        int sI = __ldg(&csr[i]);
        float w = 1.f;
        if (SRC_SCALE) w *= __ldg(&sscale[sI]);
        if (PAIRW)     w *= __ldg(&pw[i]);
        float4 x = *(const float4*)&src[(size_t)sI * C + lane * 4];
        ax = fmaf(w, x.x, ax); ay = fmaf(w, x.y, ay);
        az = fmaf(w, x.z, az); aw = fmaf(w, x.w, aw);
    }
    float os = oscale ? __ldg(&oscale[row]) : 1.f;
    ax *= os; ay *= os; az *= os; aw *= os;
    if (ELU) {
        ax = ax > 0.f ? ax : expm1f(ax);
        ay = ay > 0.f ? ay : expm1f(ay);
        az = az > 0.f ? az : expm1f(az);
        aw = aw > 0.f ? aw : expm1f(aw);
    }
    *(float4*)&dst[(size_t)row * C + lane * 4] = make_float4(ax, ay, az, aw);
}

// ---------------- launch ------------------------------------------------------
extern "C" void kernel_launch(void* const* d_in, const int* in_sizes, int n_in,
                              void* d_out, int out_size) {
    const float* X      = (const float*)d_in[0];
    const int*   pair_v = (const int*)d_in[1];
    const int*   pair_e = (const int*)d_in[2];
    const int*   src_v  = (const int*)d_in[3];
    const float* Wt     = (const float*)d_in[4];
    const float* bt     = (const float*)d_in[5];
    const float* wsrc   = (const float*)d_in[6];
    const float* wdst   = (const float*)d_in[7];
    float* out = (float*)d_out;

    void *pH, *pE, *pV, *ps, *pd, *pcv, *pce, *pov, *poe, *pcurv, *pcure;
    void *pdvi, *pinvde, *pinvdv, *palpha, *pcsrvs, *pcsres, *ppartv, *pparte;
    cudaGetSymbolAddress(&pH,  g_H);
    cudaGetSymbolAddress(&pE,  g_Edge);
    cudaGetSymbolAddress(&pV,  g_Vert);
    cudaGetSymbolAddress(&ps,  g_s);
    cudaGetSymbolAddress(&pd,  g_d);
    cudaGetSymbolAddress(&pcv, g_cnt_v);
    cudaGetSymbolAddress(&pce, g_cnt_e);
    cudaGetSymbolAddress(&pov, g_off_v);
    cudaGetSymbolAddress(&poe, g_off_e);
    cudaGetSymbolAddress(&pcurv, g_cur_v);
    cudaGetSymbolAddress(&pcure, g_cur_e);
    cudaGetSymbolAddress(&pdvi,   g_dvi);
    cudaGetSymbolAddress(&pinvde, g_inv_de);
    cudaGetSymbolAddress(&pinvdv, g_inv_dv);
    cudaGetSymbolAddress(&palpha, g_alpha);
    cudaGetSymbolAddress(&pcsrvs, g_csr_v_src);
    cudaGetSymbolAddress(&pcsres, g_csr_e_src);
    cudaGetSymbolAddress(&ppartv, g_part_v);
    cudaGetSymbolAddress(&pparte, g_part_e);

    const float* H      = (const float*)pH;
    float*       Ebuf   = (float*)pE;
    float*       Vbuf   = (float*)pV;
    const float* dvi    = (const float*)pdvi;
    const float* inv_de = (const float*)pinvde;
    const float* inv_dv = (const float*)pinvdv;
    const float* alpha  = (const float*)palpha;
    const int*   csr_v  = (const int*)pcsrvs;
    const int*   csr_e  = (const int*)pcsres;
    const int*   off_v  = (const int*)pov;
    const int*   off_e  = (const int*)poe;

    const int TB = 256;
    const int WPB = TB / 32;
    const int pairBlocks = (PP + TB - 1) / TB;
    const int gemmBlocks = (NV + 127) / 128;
    const int eRowBlocks = (ME + WPB - 1) / WPB;
    const int vRowBlocks = (NV + WPB - 1) / WPB;
    const int nbV = (NV + SCAN_B - 1) / SCAN_B;
    const int nbE = (ME + SCAN_B - 1) / SCAN_B;

    // 1) H = X W^T + b
    gemm_kernel<<<gemmBlocks, TB>>>(X, Wt, bt, (float*)pH, NV);
    // 2) s, d
    sd_kernel<<<(NV * 32 + TB - 1) / TB, TB>>>(H, wsrc, wdst, (float*)ps, (float*)pd);

    // 3) CSR build
    cudaMemsetAsync(pcv, 0, NV * sizeof(int));
    cudaMemsetAsync(pce, 0, ME * sizeof(int));
    hist_kernel<<<pairBlocks, TB>>>(pair_v, pair_e);
    scan_reduce_kernel<<<nbV, SCAN_B>>>((const int*)pcv, (int*)ppartv, NV);
    scan_reduce_kernel<<<nbE, SCAN_B>>>((const int*)pce, (int*)pparte, ME);
    scan_partials_kernel<<<1, SCAN_B>>>((int*)ppartv, nbV);
    scan_partials_kernel<<<1, SCAN_B>>>((int*)pparte, nbE);
    scan_apply_kernel<<<nbV, SCAN_B>>>((const int*)pcv, (const int*)ppartv,
                                       (int*)pov, (int*)pcurv, NV);
    scan_apply_kernel<<<nbE, SCAN_B>>>((const int*)pce, (const int*)pparte,
                                       (int*)poe, (int*)pcure, ME);
    fill_kernel<<<pairBlocks, TB>>>(pair_v, pair_e, src_v);
    finalize_v_kernel<<<(NV + TB - 1) / TB, TB>>>();
    finalize_e_kernel<<<(ME + TB - 1) / TB, TB>>>();

    // 4) softmax alpha (per CSR_v slot)
    softmax_kernel<<<vRowBlocks, TB>>>((const float*)ps, (const float*)pd);

    // 5) feature passes (all gather, no atomics)
    // P1: Edge = Xe = inv_de * segsum_e( H[v] * dvi[v] )
    gather_kernel<true, false, false><<<eRowBlocks, TB>>>(
        H, Ebuf, csr_e, off_e, dvi, nullptr, inv_de, ME);
    // P2: Vert = Hs = dvi[v] * segsum_v( Edge[e] )
    gather_kernel<false, false, false><<<vRowBlocks, TB>>>(
        Ebuf, Vbuf, csr_v, off_v, nullptr, nullptr, dvi, NV);
    // P3: Edge = Xe1 = inv_de * segsum_e( Vert[v] )
    gather_kernel<false, false, false><<<eRowBlocks, TB>>>(
        Vbuf, Ebuf, csr_e, off_e, nullptr, nullptr, inv_de, ME);
    // P4: Vert = Xv1 = segsum_v( alpha_slot * Edge[e] )
    gather_kernel<false, true, false><<<vRowBlocks, TB>>>(
        Ebuf, Vbuf, csr_v, off_v, nullptr, alpha, nullptr, NV);
    // P5: Edge = Xe2 = inv_de * segsum_e( Vert[v] )
    gather_kernel<false, false, false><<<eRowBlocks, TB>>>(
        Vbuf, Ebuf, csr_e, off_e, nullptr, nullptr, inv_de, ME);
    // P6: out = elu( inv_dv * segsum_v( Edge[e] ) )
    gather_kernel<false, false, true><<<vRowBlocks, TB>>>(
        Ebuf, out, csr_v, off_v, nullptr, nullptr, inv_dv, NV);
}

// round 5
// speedup vs baseline: 5.9219x; 1.1995x over previous
#include <cuda_runtime.h>
#include <cuda_fp16.h>
#include <cstdint>

#define NV   100000
#define ME   50000
#define PP   1600000
#define C    128
#define NEG_SLOPE 0.2f
#define SCAN_B 1024

// ---------------- scratch (device globals; no allocations allowed) ----------
__device__ float  g_H[(size_t)NV * C];       // H fp32 (for s,d)
__device__ __half g_H16[(size_t)NV * C];     // H fp16 (gather source)
__device__ __half g_Edge[(size_t)ME * C];    // edge feature buffer (fp16, reused)
__device__ __half g_Vert[(size_t)NV * C];    // vertex feature buffer (fp16, reused)
__device__ float g_s[NV];
__device__ float g_d[NV];
__device__ float g_inv_dv[NV];
__device__ float g_dvi[NV];                  // dv^-1/2
__device__ float g_inv_de[ME];
__device__ float g_alpha[PP];                // per-slot (CSR_v order) softmax weight

__device__ int g_cnt_v[NV];
__device__ int g_cnt_e[ME];
__device__ int g_off_v[NV + 1];
__device__ int g_off_e[ME + 1];
__device__ int g_cur_v[NV];
__device__ int g_cur_e[ME];
__device__ int g_csr_v_src[PP];              // edge id per vertex-grouped slot
__device__ int g_csr_v_sv[PP];               // src_v per vertex-grouped slot
__device__ int g_csr_e_src[PP];              // vertex id per edge-grouped slot
__device__ int g_part_v[256];                // scan partials
__device__ int g_part_e[256];

// ---------------- GEMM: H[i][j] = sum_k X[i][k]*W[j][k] + b[j] --------------
__global__ void gemm_kernel(const float* __restrict__ X,
                            const float* __restrict__ W,
                            const float* __restrict__ b,
                            float* __restrict__ H,
                            __half* __restrict__ H16, int nrows) {
    __shared__ float As[8][128];
    __shared__ float Bs[8][128];
    const int tid  = threadIdx.x;
    const int row0 = blockIdx.x * 128;
    const int tx = tid % 16;
    const int ty = tid / 16;
    const int lr = tid / 2;
    const int lc = (tid % 2) * 4;

    float acc[8][8];
#pragma unroll
    for (int i = 0; i < 8; i++)
#pragma unroll
        for (int j = 0; j < 8; j++) acc[i][j] = 0.f;

    for (int k0 = 0; k0 < C; k0 += 8) {
        float4 xv = make_float4(0.f, 0.f, 0.f, 0.f);
        int gr = row0 + lr;
        if (gr < nrows) xv = *(const float4*)&X[(size_t)gr * C + k0 + lc];
        As[lc + 0][lr] = xv.x; As[lc + 1][lr] = xv.y;
        As[lc + 2][lr] = xv.z; As[lc + 3][lr] = xv.w;
        float4 wv = *(const float4*)&W[(size_t)lr * C + k0 + lc];
        Bs[lc + 0][lr] = wv.x; Bs[lc + 1][lr] = wv.y;
        Bs[lc + 2][lr] = wv.z; Bs[lc + 3][lr] = wv.w;
        __syncthreads();
#pragma unroll
        for (int k = 0; k < 8; k++) {
            float a[8], bb[8];
#pragma unroll
            for (int i = 0; i < 8; i++) a[i] = As[k][ty * 8 + i];
#pragma unroll
            for (int j = 0; j < 8; j++) bb[j] = Bs[k][tx * 8 + j];
#pragma unroll
            for (int i = 0; i < 8; i++)
#pragma unroll
                for (int j = 0; j < 8; j++) acc[i][j] = fmaf(a[i], bb[j], acc[i][j]);
        }
        __syncthreads();
    }
#pragma unroll
    for (int i = 0; i < 8; i++) {
        int r = row0 + ty * 8 + i;
        if (r < nrows) {
#pragma unroll
            for (int j = 0; j < 8; j++) {
                int c = tx * 8 + j;
                H[(size_t)r * C + c] = acc[i][j] + b[c];
            }
#pragma unroll
            for (int j = 0; j < 8; j += 2) {
                int c = tx * 8 + j;
                __half2 hh = __floats2half2_rn(acc[i][j] + b[c], acc[i][j + 1] + b[c + 1]);
                *(__half2*)&H16[(size_t)r * C + c] = hh;
            }
        }
    }
}

// ---------------- s = H w_src, d = H w_dst (warp per row) -------------------
__global__ void sd_kernel(const float* __restrict__ H,
                          const float* __restrict__ wsrc,
                          const float* __restrict__ wdst,
                          float* __restrict__ s, float* __restrict__ d) {
    int w = (blockIdx.x * blockDim.x + threadIdx.x) >> 5;
    int lane = threadIdx.x & 31;
    if (w >= NV) return;
    float4 h = *(const float4*)&H[(size_t)w * C + lane * 4];
    float4 a = *(const float4*)&wsrc[lane * 4];
    float4 bb = *(const float4*)&wdst[lane * 4];
    float ss = h.x * a.x + h.y * a.y + h.z * a.z + h.w * a.w;
    float dd = h.x * bb.x + h.y * bb.y + h.z * bb.z + h.w * bb.w;
#pragma unroll
    for (int o = 16; o; o >>= 1) {
        ss += __shfl_xor_sync(0xffffffffu, ss, o);
        dd += __shfl_xor_sync(0xffffffffu, dd, o);
    }
    if (lane == 0) { s[w] = ss; d[w] = dd; }
}

// ---------------- CSR build: histogram -------------------------------------
__global__ void hist_kernel(const int* __restrict__ pv, const int* __restrict__ pe) {
    int p = blockIdx.x * blockDim.x + threadIdx.x;
    if (p >= PP) return;
    atomicAdd(&g_cnt_v[pv[p]], 1);
    atomicAdd(&g_cnt_e[pe[p]], 1);
}

// ---------------- 3-phase exclusive scan ------------------------------------
__global__ void scan_reduce_kernel(const int* __restrict__ in, int* __restrict__ part, int n) {
    __shared__ int wsum[32];
    int i = blockIdx.x * SCAN_B + threadIdx.x;
    int v = (i < n) ? in[i] : 0;
    int lane = threadIdx.x & 31, wid = threadIdx.x >> 5;
#pragma unroll
    for (int o = 16; o; o >>= 1) v += __shfl_xor_sync(0xffffffffu, v, o);
    if (lane == 0) wsum[wid] = v;
    __syncthreads();
    if (wid == 0) {
        int x = (lane < (SCAN_B >> 5)) ? wsum[lane] : 0;
#pragma unroll
        for (int o = 16; o; o >>= 1) x += __shfl_xor_sync(0xffffffffu, x, o);
        if (lane == 0) part[blockIdx.x] = x;
    }
}
__global__ void scan_partials_kernel(int* __restrict__ part, int nb) {
    __shared__ int wsum[32];
    int tid = threadIdx.x, lane = tid & 31, wid = tid >> 5;
    int v = (tid < nb) ? part[tid] : 0;
    int x = v;
#pragma unroll
    for (int o = 1; o < 32; o <<= 1) {
        int t = __shfl_up_sync(0xffffffffu, x, o);
        if (lane >= o) x += t;
    }
    if (lane == 31) wsum[wid] = x;
    __syncthreads();
    if (wid == 0) {
        int w = (lane < 32) ? wsum[lane] : 0;
#pragma unroll
        for (int o = 1; o < 32; o <<= 1) {
            int t = __shfl_up_sync(0xffffffffu, w, o);
            if (lane >= o) w += t;
        }
        wsum[lane] = w;
    }
    __syncthreads();
    int off = (wid == 0) ? 0 : wsum[wid - 1];
    if (tid < nb) part[tid] = off + x - v;     // exclusive
}
// phase 3: exclusive scan + carry; writes off, cur, and degree scales
__global__ void scan_apply_kernel(const int* __restrict__ in,
                                  const int* __restrict__ part,
                                  int* __restrict__ off, int* __restrict__ cur,
                                  float* __restrict__ invd,   // 1/deg
                                  float* __restrict__ disqrt, // deg^-1/2 (nullable)
                                  int n) {
    __shared__ int wsum[32];
    int i = blockIdx.x * SCAN_B + threadIdx.x;
    int lane = threadIdx.x & 31, wid = threadIdx.x >> 5;
    int v = (i < n) ? in[i] : 0;
    int x = v;
#pragma unroll
    for (int o = 1; o < 32; o <<= 1) {
        int t = __shfl_up_sync(0xffffffffu, x, o);
        if (lane >= o) x += t;
    }
    if (lane == 31) wsum[wid] = x;
    __syncthreads();
    if (wid == 0) {
        int w = (lane < (SCAN_B >> 5)) ? wsum[lane] : 0;
#pragma unroll
        for (int o = 1; o < 32; o <<= 1) {
            int t = __shfl_up_sync(0xffffffffu, w, o);
            if (lane >= o) w += t;
        }
        wsum[lane] = w;
    }
    __syncthreads();
    int woff = (wid == 0) ? 0 : wsum[wid - 1];
    if (i < n) {
        int val = part[blockIdx.x] + woff + x - v;
        off[i] = val;
        cur[i] = val;
        float deg = (float)max(v, 1);
        invd[i] = 1.f / deg;
        if (disqrt) disqrt[i] = rsqrtf(deg);
    }
    if (i == 0) off[n] = PP;
}

// ---------------- CSR fill (direct source indices) ---------------------------
__global__ void fill_kernel(const int* __restrict__ pv, const int* __restrict__ pe,
                            const int* __restrict__ sv) {
    int p = blockIdx.x * blockDim.x + threadIdx.x;
    if (p >= PP) return;
    int v = pv[p], e = pe[p];
    int slot_v = atomicAdd(&g_cur_v[v], 1);
    g_csr_v_src[slot_v] = e;
    g_csr_v_sv[slot_v]  = sv[p];
    int slot_e = atomicAdd(&g_cur_e[e], 1);
    g_csr_e_src[slot_e] = v;
}

// ---------------- softmax: warp per vertex over CSR_v -----------------------
__device__ __forceinline__ float slot_score(const float* s, int i, float dval) {
    float x = __ldg(&s[g_csr_v_sv[i]]) + dval;
    x = x > 0.f ? x : NEG_SLOPE * x;
    return fminf(fmaxf(x, 0.001f), 5.0f);
}

__global__ void softmax_kernel(const float* __restrict__ s,
                               const float* __restrict__ d) {
    int v = blockIdx.x * (blockDim.x >> 5) + (threadIdx.x >> 5);
    if (v >= NV) return;
    int lane = threadIdx.x & 31;
    int beg = g_off_v[v], end = g_off_v[v + 1];
    if (beg == end) return;
    float dval = __ldg(&d[v]);
    float mx = -1e30f;
    for (int i = beg + lane; i < end; i += 32)
        mx = fmaxf(mx, slot_score(s, i, dval));
#pragma unroll
    for (int o = 16; o; o >>= 1) mx = fmaxf(mx, __shfl_xor_sync(0xffffffffu, mx, o));
    float sum = 0.f;
    for (int i = beg + lane; i < end; i += 32)
        sum += __expf(slot_score(s, i, dval) - mx);
#pragma unroll
    for (int o = 16; o; o >>= 1) sum += __shfl_xor_sync(0xffffffffu, sum, o);
    float inv = 1.f / sum;
    for (int i = beg + lane; i < end; i += 32)
        g_alpha[i] = __expf(slot_score(s, i, dval) - mx) * inv;
}

// ---------------- CSR gather segment-sum, fp16 rows (warp per output row) ---
// acc = sum_i src16[csr[i]] * (SRC_SCALE? sscale[csr[i]] :1) * (PAIRW? pw[i] :1)
// FINAL=false: dst16[row] = oscale*acc (fp16);  FINAL=true: out fp32, ELU
template<bool SRC_SCALE, bool PAIRW, bool FINAL>
__global__ void gather_kernel(const __half* __restrict__ src,
                              void* __restrict__ dstv,
                              const int* __restrict__ csr,
                              const int* __restrict__ off,
                              const float* __restrict__ sscale,
                              const float* __restrict__ pw,
                              const float* __restrict__ oscale,
                              int nrows) {
    int row = blockIdx.x * (blockDim.x >> 5) + (threadIdx.x >> 5);
    if (row >= nrows) return;
    int lane = threadIdx.x & 31;
    int beg = __ldg(&off[row]), end = __ldg(&off[row + 1]);
    const uint2* s2 = (const uint2*)src;   // 8B = 4 halfs per lane
    float ax = 0.f, ay = 0.f, az = 0.f, aw = 0.f;
    int i = beg;
    for (; i + 4 <= end; i += 4) {
        int sI[4]; float w[4];
#pragma unroll
        for (int u = 0; u < 4; u++) sI[u] = __ldg(&csr[i + u]);
#pragma unroll
        for (int u = 0; u < 4; u++) {
            w[u] = 1.f;
            if (SRC_SCALE) w[u] *= __ldg(&sscale[sI[u]]);
            if (PAIRW)     w[u] *= __ldg(&pw[i + u]);
        }
#pragma unroll
        for (int u = 0; u < 4; u++) {
            uint2 r = __ldg(&s2[(size_t)sI[u] * 32 + lane]);
            float2 f0 = __half22float2(*(__half2*)&r.x);
            float2 f1 = __half22float2(*(__half2*)&r.y);
            ax = fmaf(w[u], f0.x, ax); ay = fmaf(w[u], f0.y, ay);
            az = fmaf(w[u], f1.x, az); aw = fmaf(w[u], f1.y, aw);
        }
    }
    for (; i < end; i++) {
        int sI = __ldg(&csr[i]);
        float w = 1.f;
        if (SRC_SCALE) w *= __ldg(&sscale[sI]);
        if (PAIRW)     w *= __ldg(&pw[i]);
        uint2 r = __ldg(&s2[(size_t)sI * 32 + lane]);
        float2 f0 = __half22float2(*(__half2*)&r.x);
        float2 f1 = __half22float2(*(__half2*)&r.y);
        ax = fmaf(w, f0.x, ax); ay = fmaf(w, f0.y, ay);
        az = fmaf(w, f1.x, az); aw = fmaf(w, f1.y, aw);
    }
    float os = oscale ? __ldg(&oscale[row]) : 1.f;
    ax *= os; ay *= os; az *= os; aw *= os;
    if (FINAL) {
        ax = ax > 0.f ? ax : expm1f(ax);
        ay = ay > 0.f ? ay : expm1f(ay);
        az = az > 0.f ? az : expm1f(az);
        aw = aw > 0.f ? aw : expm1f(aw);
        *(float4*)&((float*)dstv)[(size_t)row * C + lane * 4] =
            make_float4(ax, ay, az, aw);
    } else {
        uint2 o;
        __half2 o0 = __floats2half2_rn(ax, ay);
        __half2 o1 = __floats2half2_rn(az, aw);
        o.x = *(unsigned*)&o0; o.y = *(unsigned*)&o1;
        ((uint2*)dstv)[(size_t)row * 32 + lane] = o;
    }
}

// ---------------- launch ------------------------------------------------------
extern "C" void kernel_launch(void* const* d_in, const int* in_sizes, int n_in,
                              void* d_out, int out_size) {
    const float* X      = (const float*)d_in[0];
    const int*   pair_v = (const int*)d_in[1];
    const int*   pair_e = (const int*)d_in[2];
    const int*   src_v  = (const int*)d_in[3];
    const float* Wt     = (const float*)d_in[4];
    const float* bt     = (const float*)d_in[5];
    const float* wsrc   = (const float*)d_in[6];
    const float* wdst   = (const float*)d_in[7];
    float* out = (float*)d_out;

    void *pH, *pH16, *pE, *pV, *ps, *pd, *pcv, *pce, *pov, *poe, *pcurv, *pcure;
    void *pdvi, *pinvde, *pinvdv, *palpha, *pcsrvs, *pcsres, *ppartv, *pparte;
    cudaGetSymbolAddress(&pH,   g_H);
    cudaGetSymbolAddress(&pH16, g_H16);
    cudaGetSymbolAddress(&pE,   g_Edge);
    cudaGetSymbolAddress(&pV,   g_Vert);
    cudaGetSymbolAddress(&ps,   g_s);
    cudaGetSymbolAddress(&pd,   g_d);
    cudaGetSymbolAddress(&pcv,  g_cnt_v);
    cudaGetSymbolAddress(&pce,  g_cnt_e);
    cudaGetSymbolAddress(&pov,  g_off_v);
    cudaGetSymbolAddress(&poe,  g_off_e);
    cudaGetSymbolAddress(&pcurv, g_cur_v);
    cudaGetSymbolAddress(&pcure, g_cur_e);
    cudaGetSymbolAddress(&pdvi,   g_dvi);
    cudaGetSymbolAddress(&pinvde, g_inv_de);
    cudaGetSymbolAddress(&pinvdv, g_inv_dv);
    cudaGetSymbolAddress(&palpha, g_alpha);
    cudaGetSymbolAddress(&pcsrvs, g_csr_v_src);
    cudaGetSymbolAddress(&pcsres, g_csr_e_src);
    cudaGetSymbolAddress(&ppartv, g_part_v);
    cudaGetSymbolAddress(&pparte, g_part_e);

    const float*  H      = (const float*)pH;
    const __half* H16    = (const __half*)pH16;
    __half*       Ebuf   = (__half*)pE;
    __half*       Vbuf   = (__half*)pV;
    const float*  dvi    = (const float*)pdvi;
    const float*  inv_de = (const float*)pinvde;
    const float*  inv_dv = (const float*)pinvdv;
    const float*  alpha  = (const float*)palpha;
    const int*    csr_v  = (const int*)pcsrvs;
    const int*    csr_e  = (const int*)pcsres;
    const int*    off_v  = (const int*)pov;
    const int*    off_e  = (const int*)poe;

    const int TB = 256;
    const int WPB = TB / 32;
    const int pairBlocks = (PP + TB - 1) / TB;
    const int gemmBlocks = (NV + 127) / 128;
    const int eRowBlocks = (ME + WPB - 1) / WPB;
    const int vRowBlocks = (NV + WPB - 1) / WPB;
    const int nbV = (NV + SCAN_B - 1) / SCAN_B;
    const int nbE = (ME + SCAN_B - 1) / SCAN_B;

    // 1) H = X W^T + b  (fp32 + fp16 copies)
    gemm_kernel<<<gemmBlocks, TB>>>(X, Wt, bt, (float*)pH, (__half*)pH16, NV);
    // 2) s, d from fp32 H
    sd_kernel<<<(NV * 32 + TB - 1) / TB, TB>>>(H, wsrc, wdst, (float*)ps, (float*)pd);

    // 3) CSR build (+ fused degree scales)
    cudaMemsetAsync(pcv, 0, NV * sizeof(int));
    cudaMemsetAsync(pce, 0, ME * sizeof(int));
    hist_kernel<<<pairBlocks, TB>>>(pair_v, pair_e);
    scan_reduce_kernel<<<nbV, SCAN_B>>>((const int*)pcv, (int*)ppartv, NV);
    scan_reduce_kernel<<<nbE, SCAN_B>>>((const int*)pce, (int*)pparte, ME);
    scan_partials_kernel<<<1, SCAN_B>>>((int*)ppartv, nbV);
    scan_partials_kernel<<<1, SCAN_B>>>((int*)pparte, nbE);
    scan_apply_kernel<<<nbV, SCAN_B>>>((const int*)pcv, (const int*)ppartv,
                                       (int*)pov, (int*)pcurv,
                                       (float*)pinvdv, (float*)pdvi, NV);
    scan_apply_kernel<<<nbE, SCAN_B>>>((const int*)pce, (const int*)pparte,
                                       (int*)poe, (int*)pcure,
                                       (float*)pinvde, nullptr, ME);
    fill_kernel<<<pairBlocks, TB>>>(pair_v, pair_e, src_v);

    // 4) softmax alpha (per CSR_v slot)
    softmax_kernel<<<vRowBlocks, TB>>>((const float*)ps, (const float*)pd);

    // 5) feature passes (all gather, no atomics, fp16 rows)
    // P1: Edge = Xe = inv_de * segsum_e( H[v] * dvi[v] )
    gather_kernel<true, false, false><<<eRowBlocks, TB>>>(
        H16, Ebuf, csr_e, off_e, dvi, nullptr, inv_de, ME);
    // P2: Vert = Hs = dvi[v] * segsum_v( Edge[e] )
    gather_kernel<false, false, false><<<vRowBlocks, TB>>>(
        Ebuf, Vbuf, csr_v, off_v, nullptr, nullptr, dvi, NV);
    // P3: Edge = Xe1 = inv_de * segsum_e( Vert[v] )
    gather_kernel<false, false, false><<<eRowBlocks, TB>>>(
        Vbuf, Ebuf, csr_e, off_e, nullptr, nullptr, inv_de, ME);
    // P4: Vert = Xv1 = segsum_v( alpha_slot * Edge[e] )
    gather_kernel<false, true, false><<<vRowBlocks, TB>>>(
        Ebuf, Vbuf, csr_v, off_v, nullptr, alpha, nullptr, NV);
    // P5: Edge = Xe2 = inv_de * segsum_e( Vert[v] )
    gather_kernel<false, false, false><<<eRowBlocks, TB>>>(
        Vbuf, Ebuf, csr_e, off_e, nullptr, nullptr, inv_de, ME);
    // P6: out = elu( inv_dv * segsum_v( Edge[e] ) )  (fp32 out)
    gather_kernel<false, false, true><<<vRowBlocks, TB>>>(
        Ebuf, out, csr_v, off_v, nullptr, nullptr, inv_dv, NV);
}

// round 6
// speedup vs baseline: 5.9299x; 1.0014x over previous
#include <cuda_runtime.h>
#include <cuda_fp16.h>
#include <cstdint>

#define NV   100000
#define ME   50000
#define PP   1600000
#define C    128
#define NEG_SLOPE 0.2f
#define SCAN_B 1024

// ---------------- scratch (device globals; no allocations allowed) ----------
__device__ __half g_H16[(size_t)NV * C];     // H fp16 (gather source)
__device__ __half g_Edge[(size_t)ME * C];    // edge feature buffer (fp16, reused)
__device__ __half g_Vert[(size_t)NV * C];    // vertex feature buffer (fp16, reused)
__device__ float g_s[NV];
__device__ float g_d[NV];
__device__ float g_inv_dv[NV];
__device__ float g_dvi[NV];                  // dv^-1/2
__device__ float g_inv_de[ME];
__device__ float g_alpha[PP];                // per-slot (CSR_v order) softmax weight
__device__ float g_uw[2 * C + 2];            // projected wsrc/wdst + consts

__device__ int g_cnt_v[NV];
__device__ int g_cnt_e[ME];
__device__ int g_off_v[NV + 1];
__device__ int g_off_e[ME + 1];
__device__ int g_cur_v[NV];
__device__ int g_cur_e[ME];
__device__ int g_csr_v_src[PP];              // edge id per vertex-grouped slot
__device__ int g_csr_v_sv[PP];               // src_v per vertex-grouped slot
__device__ int g_csr_e_src[PP];              // vertex id per edge-grouped slot
__device__ int g_part_v[256];                // scan partials
__device__ int g_part_e[256];

// ---------------- GEMM: H16[i][j] = fp16( sum_k X[i][k]*W[j][k] + b[j] ) ----
__global__ void gemm_kernel(const float* __restrict__ X,
                            const float* __restrict__ W,
                            const float* __restrict__ b,
                            __half* __restrict__ H16, int nrows) {
    __shared__ float As[8][128];
    __shared__ float Bs[8][128];
    const int tid  = threadIdx.x;
    const int row0 = blockIdx.x * 128;
    const int tx = tid % 16;
    const int ty = tid / 16;
    const int lr = tid / 2;
    const int lc = (tid % 2) * 4;

    float acc[8][8];
#pragma unroll
    for (int i = 0; i < 8; i++)
#pragma unroll
        for (int j = 0; j < 8; j++) acc[i][j] = 0.f;

    for (int k0 = 0; k0 < C; k0 += 8) {
        float4 xv = make_float4(0.f, 0.f, 0.f, 0.f);
        int gr = row0 + lr;
        if (gr < nrows) xv = *(const float4*)&X[(size_t)gr * C + k0 + lc];
        As[lc + 0][lr] = xv.x; As[lc + 1][lr] = xv.y;
        As[lc + 2][lr] = xv.z; As[lc + 3][lr] = xv.w;
        float4 wv = *(const float4*)&W[(size_t)lr * C + k0 + lc];
        Bs[lc + 0][lr] = wv.x; Bs[lc + 1][lr] = wv.y;
        Bs[lc + 2][lr] = wv.z; Bs[lc + 3][lr] = wv.w;
        __syncthreads();
#pragma unroll
        for (int k = 0; k < 8; k++) {
            float a[8], bb[8];
#pragma unroll
            for (int i = 0; i < 8; i++) a[i] = As[k][ty * 8 + i];
#pragma unroll
            for (int j = 0; j < 8; j++) bb[j] = Bs[k][tx * 8 + j];
#pragma unroll
            for (int i = 0; i < 8; i++)
#pragma unroll
                for (int j = 0; j < 8; j++) acc[i][j] = fmaf(a[i], bb[j], acc[i][j]);
        }
        __syncthreads();
    }
#pragma unroll
    for (int i = 0; i < 8; i++) {
        int r = row0 + ty * 8 + i;
        if (r < nrows) {
#pragma unroll
            for (int j = 0; j < 8; j += 2) {
                int c = tx * 8 + j;
                __half2 hh = __floats2half2_rn(acc[i][j] + b[c], acc[i][j + 1] + b[c + 1]);
                *(__half2*)&H16[(size_t)r * C + c] = hh;
            }
        }
    }
}

// ---------------- prep: uw = W^T wsrc / W^T wdst + b dots --------------------
__global__ void prep_uw_kernel(const float* __restrict__ W,
                               const float* __restrict__ b,
                               const float* __restrict__ wsrc,
                               const float* __restrict__ wdst) {
    int k = threadIdx.x;          // 128 threads
    float a = 0.f, c = 0.f;
#pragma unroll 8
    for (int j = 0; j < C; j++) {
        float wj = W[(size_t)j * C + k];
        a = fmaf(wj, wsrc[j], a);
        c = fmaf(wj, wdst[j], c);
    }
    g_uw[k] = a;
    g_uw[C + k] = c;
    if (k == 0) {
        float cs = 0.f, cd = 0.f;
        for (int j = 0; j < C; j++) { cs += b[j] * wsrc[j]; cd += b[j] * wdst[j]; }
        g_uw[2 * C] = cs;
        g_uw[2 * C + 1] = cd;
    }
}

// ---------------- s = X uws + cs, d = X uwd + cd (warp per row) -------------
__global__ void sd_kernel(const float* __restrict__ X,
                          float* __restrict__ s, float* __restrict__ d) {
    int w = (blockIdx.x * blockDim.x + threadIdx.x) >> 5;
    int lane = threadIdx.x & 31;
    if (w >= NV) return;
    float4 h = *(const float4*)&X[(size_t)w * C + lane * 4];
    float4 a = *(const float4*)&g_uw[lane * 4];
    float4 bb = *(const float4*)&g_uw[C + lane * 4];
    float ss = h.x * a.x + h.y * a.y + h.z * a.z + h.w * a.w;
    float dd = h.x * bb.x + h.y * bb.y + h.z * bb.z + h.w * bb.w;
#pragma unroll
    for (int o = 16; o; o >>= 1) {
        ss += __shfl_xor_sync(0xffffffffu, ss, o);
        dd += __shfl_xor_sync(0xffffffffu, dd, o);
    }
    if (lane == 0) { s[w] = ss + g_uw[2 * C]; d[w] = dd + g_uw[2 * C + 1]; }
}

// ---------------- CSR build: histogram -------------------------------------
__global__ void hist_kernel(const int* __restrict__ pv, const int* __restrict__ pe) {
    int p = blockIdx.x * blockDim.x + threadIdx.x;
    if (p >= PP) return;
    atomicAdd(&g_cnt_v[pv[p]], 1);
    atomicAdd(&g_cnt_e[pe[p]], 1);
}

// ---------------- 3-phase exclusive scan ------------------------------------
__global__ void scan_reduce_kernel(const int* __restrict__ in, int* __restrict__ part, int n) {
    __shared__ int wsum[32];
    int i = blockIdx.x * SCAN_B + threadIdx.x;
    int v = (i < n) ? in[i] : 0;
    int lane = threadIdx.x & 31, wid = threadIdx.x >> 5;
#pragma unroll
    for (int o = 16; o; o >>= 1) v += __shfl_xor_sync(0xffffffffu, v, o);
    if (lane == 0) wsum[wid] = v;
    __syncthreads();
    if (wid == 0) {
        int x = (lane < (SCAN_B >> 5)) ? wsum[lane] : 0;
#pragma unroll
        for (int o = 16; o; o >>= 1) x += __shfl_xor_sync(0xffffffffu, x, o);
        if (lane == 0) part[blockIdx.x] = x;
    }
}
__global__ void scan_partials_kernel(int* __restrict__ part, int nb) {
    __shared__ int wsum[32];
    int tid = threadIdx.x, lane = tid & 31, wid = tid >> 5;
    int v = (tid < nb) ? part[tid] : 0;
    int x = v;
#pragma unroll
    for (int o = 1; o < 32; o <<= 1) {
        int t = __shfl_up_sync(0xffffffffu, x, o);
        if (lane >= o) x += t;
    }
    if (lane == 31) wsum[wid] = x;
    __syncthreads();
    if (wid == 0) {
        int w = (lane < 32) ? wsum[lane] : 0;
#pragma unroll
        for (int o = 1; o < 32; o <<= 1) {
            int t = __shfl_up_sync(0xffffffffu, w, o);
            if (lane >= o) w += t;
        }
        wsum[lane] = w;
    }
    __syncthreads();
    int off = (wid == 0) ? 0 : wsum[wid - 1];
    if (tid < nb) part[tid] = off + x - v;     // exclusive
}
__global__ void scan_apply_kernel(const int* __restrict__ in,
                                  const int* __restrict__ part,
                                  int* __restrict__ off, int* __restrict__ cur,
                                  float* __restrict__ invd,
                                  float* __restrict__ disqrt,
                                  int n) {
    __shared__ int wsum[32];
    int i = blockIdx.x * SCAN_B + threadIdx.x;
    int lane = threadIdx.x & 31, wid = threadIdx.x >> 5;
    int v = (i < n) ? in[i] : 0;
    int x = v;
#pragma unroll
    for (int o = 1; o < 32; o <<= 1) {
        int t = __shfl_up_sync(0xffffffffu, x, o);
        if (lane >= o) x += t;
    }
    if (lane == 31) wsum[wid] = x;
    __syncthreads();
    if (wid == 0) {
        int w = (lane < (SCAN_B >> 5)) ? wsum[lane] : 0;
#pragma unroll
        for (int o = 1; o < 32; o <<= 1) {
            int t = __shfl_up_sync(0xffffffffu, w, o);
            if (lane >= o) w += t;
        }
        wsum[lane] = w;
    }
    __syncthreads();
    int woff = (wid == 0) ? 0 : wsum[wid - 1];
    if (i < n) {
        int val = part[blockIdx.x] + woff + x - v;
        off[i] = val;
        cur[i] = val;
        float deg = (float)max(v, 1);
        invd[i] = 1.f / deg;
        if (disqrt) disqrt[i] = rsqrtf(deg);
    }
    if (i == 0) off[n] = PP;
}

// ---------------- CSR fill (direct source indices) ---------------------------
__global__ void fill_kernel(const int* __restrict__ pv, const int* __restrict__ pe,
                            const int* __restrict__ sv) {
    int p = blockIdx.x * blockDim.x + threadIdx.x;
    if (p >= PP) return;
    int v = pv[p], e = pe[p];
    int slot_v = atomicAdd(&g_cur_v[v], 1);
    g_csr_v_src[slot_v] = e;
    g_csr_v_sv[slot_v]  = sv[p];
    int slot_e = atomicAdd(&g_cur_e[e], 1);
    g_csr_e_src[slot_e] = v;
}

// ---------------- softmax: warp per vertex, register-cached scores ----------
__device__ __forceinline__ float slot_score(const float* s, int i, float dval) {
    float x = __ldg(&s[g_csr_v_sv[i]]) + dval;
    x = x > 0.f ? x : NEG_SLOPE * x;
    return fminf(fmaxf(x, 0.001f), 5.0f);
}

__global__ void softmax_kernel(const float* __restrict__ s,
                               const float* __restrict__ d) {
    int v = blockIdx.x * (blockDim.x >> 5) + (threadIdx.x >> 5);
    if (v >= NV) return;
    int lane = threadIdx.x & 31;
    int beg = g_off_v[v], end = g_off_v[v + 1];
    int n = end - beg;
    if (n == 0) return;
    float dval = __ldg(&d[v]);
    if (n <= 128) {
        // register-cached path: one random gather total
        float sc[4];
        int k = 0;
        float mx = -1e30f;
        for (int i = beg + lane; i < end; i += 32, k++) {
            sc[k] = slot_score(s, i, dval);
            mx = fmaxf(mx, sc[k]);
        }
#pragma unroll
        for (int o = 16; o; o >>= 1) mx = fmaxf(mx, __shfl_xor_sync(0xffffffffu, mx, o));
        float sum = 0.f;
        k = 0;
        for (int i = beg + lane; i < end; i += 32, k++) {
            sc[k] = __expf(sc[k] - mx);
            sum += sc[k];
        }
#pragma unroll
        for (int o = 16; o; o >>= 1) sum += __shfl_xor_sync(0xffffffffu, sum, o);
        float inv = 1.f / sum;
        k = 0;
        for (int i = beg + lane; i < end; i += 32, k++)
            g_alpha[i] = sc[k] * inv;
    } else {
        // fallback: store scores in alpha, sequential re-reads
        float mx = -1e30f;
        for (int i = beg + lane; i < end; i += 32) {
            float x = slot_score(s, i, dval);
            g_alpha[i] = x;
            mx = fmaxf(mx, x);
        }
#pragma unroll
        for (int o = 16; o; o >>= 1) mx = fmaxf(mx, __shfl_xor_sync(0xffffffffu, mx, o));
        float sum = 0.f;
        for (int i = beg + lane; i < end; i += 32) {
            float e = __expf(g_alpha[i] - mx);
            g_alpha[i] = e;
            sum += e;
        }
#pragma unroll
        for (int o = 16; o; o >>= 1) sum += __shfl_xor_sync(0xffffffffu, sum, o);
        float inv = 1.f / sum;
        for (int i = beg + lane; i < end; i += 32)
            g_alpha[i] *= inv;
    }
}

// ---------------- CSR gather segment-sum, fp16 rows -------------------------
// warp per output row; half-warp per pair; uint4 (8 halfs) per lane.
template<bool SRC_SCALE, bool PAIRW, bool FINAL>
__global__ void gather_kernel(const __half* __restrict__ src,
                              void* __restrict__ dstv,
                              const int* __restrict__ csr,
                              const int* __restrict__ off,
                              const float* __restrict__ sscale,
                              const float* __restrict__ pw,
                              const float* __restrict__ oscale,
                              int nrows) {
    int row = blockIdx.x * (blockDim.x >> 5) + (threadIdx.x >> 5);
    if (row >= nrows) return;
    int lane = threadIdx.x & 31;
    int half = lane >> 4;           // 0 or 1: which pair of the step
    int hl = lane & 15;             // 16 lanes cover a 256B row
    int beg = __ldg(&off[row]), end = __ldg(&off[row + 1]);
    const uint4* s4 = (const uint4*)src;     // row stride = 16 uint4
    float acc[8];
#pragma unroll
    for (int c = 0; c < 8; c++) acc[c] = 0.f;

    int i = beg;
    for (; i + 8 <= end; i += 8) {           // 8 pairs: 4 steps x 2 halves
        int idx[4]; float w[4]; uint4 r[4];
#pragma unroll
        for (int u = 0; u < 4; u++) idx[u] = __ldg(&csr[i + 2 * u + half]);
#pragma unroll
        for (int u = 0; u < 4; u++) {
            w[u] = 1.f;
            if (SRC_SCALE) w[u] *= __ldg(&sscale[idx[u]]);
            if (PAIRW)     w[u] *= __ldg(&pw[i + 2 * u + half]);
        }
#pragma unroll
        for (int u = 0; u < 4; u++) r[u] = __ldg(&s4[(size_t)idx[u] * 16 + hl]);
#pragma unroll
        for (int u = 0; u < 4; u++) {
            float2 f0 = __half22float2(*(__half2*)&r[u].x);
            float2 f1 = __half22float2(*(__half2*)&r[u].y);
            float2 f2 = __half22float2(*(__half2*)&r[u].z);
            float2 f3 = __half22float2(*(__half2*)&r[u].w);
            acc[0] = fmaf(w[u], f0.x, acc[0]); acc[1] = fmaf(w[u], f0.y, acc[1]);
            acc[2] = fmaf(w[u], f1.x, acc[2]); acc[3] = fmaf(w[u], f1.y, acc[3]);
            acc[4] = fmaf(w[u], f2.x, acc[4]); acc[5] = fmaf(w[u], f2.y, acc[5]);
            acc[6] = fmaf(w[u], f3.x, acc[6]); acc[7] = fmaf(w[u], f3.y, acc[7]);
        }
    }
    for (; i < end; i += 2) {                // 2-pair steps (+ possible odd tail)
        int j = i + half;
        if (j < end) {
            int idx = __ldg(&csr[j]);
            float w = 1.f;
            if (SRC_SCALE) w *= __ldg(&sscale[idx]);
            if (PAIRW)     w *= __ldg(&pw[j]);
            uint4 r = __ldg(&s4[(size_t)idx * 16 + hl]);
            float2 f0 = __half22float2(*(__half2*)&r.x);
            float2 f1 = __half22float2(*(__half2*)&r.y);
            float2 f2 = __half22float2(*(__half2*)&r.z);
            float2 f3 = __half22float2(*(__half2*)&r.w);
            acc[0] = fmaf(w, f0.x, acc[0]); acc[1] = fmaf(w, f0.y, acc[1]);
            acc[2] = fmaf(w, f1.x, acc[2]); acc[3] = fmaf(w, f1.y, acc[3]);
            acc[4] = fmaf(w, f2.x, acc[4]); acc[5] = fmaf(w, f2.y, acc[5]);
            acc[6] = fmaf(w, f3.x, acc[6]); acc[7] = fmaf(w, f3.y, acc[7]);
        }
    }
    // combine halves
#pragma unroll
    for (int c = 0; c < 8; c++)
        acc[c] += __shfl_xor_sync(0xffffffffu, acc[c], 16);

    float os = oscale ? __ldg(&oscale[row]) : 1.f;
#pragma unroll
    for (int c = 0; c < 8; c++) acc[c] *= os;

    if (lane < 16) {
        if (FINAL) {
#pragma unroll
            for (int c = 0; c < 8; c++)
                acc[c] = acc[c] > 0.f ? acc[c] : expm1f(acc[c]);
            float* o = (float*)dstv + (size_t)row * C + hl * 8;
            *(float4*)o       = make_float4(acc[0], acc[1], acc[2], acc[3]);
            *(float4*)(o + 4) = make_float4(acc[4], acc[5], acc[6], acc[7]);
        } else {
            __half2 h0 = __floats2half2_rn(acc[0], acc[1]);
            __half2 h1 = __floats2half2_rn(acc[2], acc[3]);
            __half2 h2 = __floats2half2_rn(acc[4], acc[5]);
            __half2 h3 = __floats2half2_rn(acc[6], acc[7]);
            uint4 o;
            o.x = *(unsigned*)&h0; o.y = *(unsigned*)&h1;
            o.z = *(unsigned*)&h2; o.w = *(unsigned*)&h3;
            ((uint4*)dstv)[(size_t)row * 16 + hl] = o;
        }
    }
}

// ---------------- launch ------------------------------------------------------
extern "C" void kernel_launch(void* const* d_in, const int* in_sizes, int n_in,
                              void* d_out, int out_size) {
    const float* X      = (const float*)d_in[0];
    const int*   pair_v = (const int*)d_in[1];
    const int*   pair_e = (const int*)d_in[2];
    const int*   src_v  = (const int*)d_in[3];
    const float* Wt     = (const float*)d_in[4];
    const float* bt     = (const float*)d_in[5];
    const float* wsrc   = (const float*)d_in[6];
    const float* wdst   = (const float*)d_in[7];
    float* out = (float*)d_out;

    void *pH16, *pE, *pV, *ps, *pd, *pcv, *pce, *pov, *poe, *pcurv, *pcure;
    void *pdvi, *pinvde, *pinvdv, *palpha, *pcsrvs, *pcsres, *ppartv, *pparte;
    cudaGetSymbolAddress(&pH16, g_H16);
    cudaGetSymbolAddress(&pE,   g_Edge);
    cudaGetSymbolAddress(&pV,   g_Vert);
    cudaGetSymbolAddress(&ps,   g_s);
    cudaGetSymbolAddress(&pd,   g_d);
    cudaGetSymbolAddress(&pcv,  g_cnt_v);
    cudaGetSymbolAddress(&pce,  g_cnt_e);
    cudaGetSymbolAddress(&pov,  g_off_v);
    cudaGetSymbolAddress(&poe,  g_off_e);
    cudaGetSymbolAddress(&pcurv, g_cur_v);
    cudaGetSymbolAddress(&pcure, g_cur_e);
    cudaGetSymbolAddress(&pdvi,   g_dvi);
    cudaGetSymbolAddress(&pinvde, g_inv_de);
    cudaGetSymbolAddress(&pinvdv, g_inv_dv);
    cudaGetSymbolAddress(&palpha, g_alpha);
    cudaGetSymbolAddress(&pcsrvs, g_csr_v_src);
    cudaGetSymbolAddress(&pcsres, g_csr_e_src);
    cudaGetSymbolAddress(&ppartv, g_part_v);
    cudaGetSymbolAddress(&pparte, g_part_e);

    const __half* H16    = (const __half*)pH16;
    __half*       Ebuf   = (__half*)pE;
    __half*       Vbuf   = (__half*)pV;
    const float*  dvi    = (const float*)pdvi;
    const float*  inv_de = (const float*)pinvde;
    const float*  inv_dv = (const float*)pinvdv;
    const float*  alpha  = (const float*)palpha;
    const int*    csr_v  = (const int*)pcsrvs;
    const int*    csr_e  = (const int*)pcsres;
    const int*    off_v  = (const int*)pov;
    const int*    off_e  = (const int*)poe;

    const int TB = 256;
    const int WPB = TB / 32;
    const int pairBlocks = (PP + TB - 1) / TB;
    const int gemmBlocks = (NV + 127) / 128;
    const int eRowBlocks = (ME + WPB - 1) / WPB;
    const int vRowBlocks = (NV + WPB - 1) / WPB;
    const int nbV = (NV + SCAN_B - 1) / SCAN_B;
    const int nbE = (ME + SCAN_B - 1) / SCAN_B;

    // 1) H16 = fp16(X W^T + b); projected attention vectors; s,d from X
    gemm_kernel<<<gemmBlocks, TB>>>(X, Wt, bt, (__half*)pH16, NV);
    prep_uw_kernel<<<1, C>>>(Wt, bt, wsrc, wdst);
    sd_kernel<<<(NV * 32 + TB - 1) / TB, TB>>>(X, (float*)ps, (float*)pd);

    // 2) CSR build (+ fused degree scales)
    cudaMemsetAsync(pcv, 0, NV * sizeof(int));
    cudaMemsetAsync(pce, 0, ME * sizeof(int));
    hist_kernel<<<pairBlocks, TB>>>(pair_v, pair_e);
    scan_reduce_kernel<<<nbV, SCAN_B>>>((const int*)pcv, (int*)ppartv, NV);
    scan_reduce_kernel<<<nbE, SCAN_B>>>((const int*)pce, (int*)pparte, ME);
    scan_partials_kernel<<<1, SCAN_B>>>((int*)ppartv, nbV);
    scan_partials_kernel<<<1, SCAN_B>>>((int*)pparte, nbE);
    scan_apply_kernel<<<nbV, SCAN_B>>>((const int*)pcv, (const int*)ppartv,
                                       (int*)pov, (int*)pcurv,
                                       (float*)pinvdv, (float*)pdvi, NV);
    scan_apply_kernel<<<nbE, SCAN_B>>>((const int*)pce, (const int*)pparte,
                                       (int*)poe, (int*)pcure,
                                       (float*)pinvde, nullptr, ME);
    fill_kernel<<<pairBlocks, TB>>>(pair_v, pair_e, src_v);

    // 3) softmax alpha (per CSR_v slot)
    softmax_kernel<<<vRowBlocks, TB>>>((const float*)ps, (const float*)pd);

    // 4) feature passes (all gather, no atomics, fp16 rows)
    // P1: Edge = Xe = inv_de * segsum_e( H[v] * dvi[v] )
    gather_kernel<true, false, false><<<eRowBlocks, TB>>>(
        H16, Ebuf, csr_e, off_e, dvi, nullptr, inv_de, ME);
    // P2: Vert = Hs = dvi[v] * segsum_v( Edge[e] )
    gather_kernel<false, false, false><<<vRowBlocks, TB>>>(
        Ebuf, Vbuf, csr_v, off_v, nullptr, nullptr, dvi, NV);
    // P3: Edge = Xe1 = inv_de * segsum_e( Vert[v] )
    gather_kernel<false, false, false><<<eRowBlocks, TB>>>(
        Vbuf, Ebuf, csr_e, off_e, nullptr, nullptr, inv_de, ME);
    // P4: Vert = Xv1 = segsum_v( alpha_slot * Edge[e] )
    gather_kernel<false, true, false><<<vRowBlocks, TB>>>(
        Ebuf, Vbuf, csr_v, off_v, nullptr, alpha, nullptr, NV);
    // P5: Edge = Xe2 = inv_de * segsum_e( Vert[v] )
    gather_kernel<false, false, false><<<eRowBlocks, TB>>>(
        Vbuf, Ebuf, csr_e, off_e, nullptr, nullptr, inv_de, ME);
    // P6: out = elu( inv_dv * segsum_v( Edge[e] ) )  (fp32 out)
    gather_kernel<false, false, true><<<vRowBlocks, TB>>>(
        Ebuf, out, csr_v, off_v, nullptr, nullptr, inv_dv, NV);
}

// round 7
// speedup vs baseline: 6.7558x; 1.1393x over previous
#include <cuda_runtime.h>
#include <cuda_fp16.h>
#include <mma.h>
#include <cstdint>

using namespace nvcuda;

#define NV   100000
#define ME   50000
#define PP   1600000
#define C    128
#define NEG_SLOPE 0.2f
#define SCAN_B 1024

// ---------------- scratch (device globals; no allocations allowed) ----------
__device__ __half g_H16[(size_t)NV * C];     // H fp16 (gather source)
__device__ __half g_Edge[(size_t)ME * C];    // edge feature buffer (fp16, reused)
__device__ __half g_Vert[(size_t)NV * C];    // vertex feature buffer (fp16, reused)
__device__ float g_s[NV];
__device__ float g_d[NV];
__device__ float g_inv_dv[NV];
__device__ float g_dvi[NV];                  // dv^-1/2
__device__ float g_inv_de[ME];
__device__ float g_alpha[PP];                // per-slot (CSR_v order) softmax weight
__device__ float g_uw[2 * C + 2];            // projected wsrc/wdst + consts

__device__ int  g_cnt_v[NV];
__device__ int  g_cnt_e[ME];
__device__ int  g_off_v[NV + 1];
__device__ int  g_off_e[ME + 1];
__device__ int  g_cur_v[NV];
__device__ int  g_cur_e[ME];
__device__ int2 g_csr_v_pack[PP];            // (edge id, src_v) per vertex-grouped slot
__device__ int  g_csr_e_src[PP];             // vertex id per edge-grouped slot
__device__ int  g_part_v[256];               // scan partials
__device__ int  g_part_e[256];

// ---------------- tensor-core GEMM: H16 = fp16(X W^T + b) -------------------
// 128x128 tile per block, 8 warps (4m x 2n), wmma 16x16x16 fp16/fp32.
__global__ void gemm_wmma_kernel(const float* __restrict__ X,
                                 const float* __restrict__ W,
                                 const float* __restrict__ bias,
                                 __half* __restrict__ H16, int nrows) {
    extern __shared__ float sH[];            // 128*128 fp32 staging (64KB dynamic)
    __shared__ __half sX[128][40];
    __shared__ __half sW[128][40];
    __shared__ float  sB[128];

    const int tid = threadIdx.x;
    const int wid = tid >> 5;
    const int row0 = blockIdx.x * 128;
    const int warp_m = wid & 3;              // 4 groups of 32 rows
    const int warp_n = wid >> 2;             // 2 groups of 64 cols

    if (tid < 128) sB[tid] = bias[tid];

    wmma::fragment<wmma::accumulator, 16, 16, 16, float> acc[2][4];
#pragma unroll
    for (int i = 0; i < 2; i++)
#pragma unroll
        for (int j = 0; j < 4; j++) wmma::fill_fragment(acc[i][j], 0.f);

    const int lr = tid >> 1;                 // 0..127 (row to load)
    const int lk = (tid & 1) * 16;           // 0 or 16 (k-offset within chunk)

    for (int k0 = 0; k0 < C; k0 += 32) {
        {   // X tile
            float4 v0, v1, v2, v3;
            int gr = row0 + lr;
            if (gr < nrows) {
                const float4* p = (const float4*)&X[(size_t)gr * C + k0 + lk];
                v0 = p[0]; v1 = p[1]; v2 = p[2]; v3 = p[3];
            } else {
                v0 = v1 = v2 = v3 = make_float4(0.f, 0.f, 0.f, 0.f);
            }
            __half2* d = (__half2*)&sX[lr][lk];
            d[0] = __floats2half2_rn(v0.x, v0.y); d[1] = __floats2half2_rn(v0.z, v0.w);
            d[2] = __floats2half2_rn(v1.x, v1.y); d[3] = __floats2half2_rn(v1.z, v1.w);
            d[4] = __floats2half2_rn(v2.x, v2.y); d[5] = __floats2half2_rn(v2.z, v2.w);
            d[6] = __floats2half2_rn(v3.x, v3.y); d[7] = __floats2half2_rn(v3.z, v3.w);
        }
        {   // W tile (row j of W = column j of W^T)
            const float4* p = (const float4*)&W[(size_t)lr * C + k0 + lk];
            float4 v0 = p[0], v1 = p[1], v2 = p[2], v3 = p[3];
            __half2* d = (__half2*)&sW[lr][lk];
            d[0] = __floats2half2_rn(v0.x, v0.y); d[1] = __floats2half2_rn(v0.z, v0.w);
            d[2] = __floats2half2_rn(v1.x, v1.y); d[3] = __floats2half2_rn(v1.z, v1.w);
            d[4] = __floats2half2_rn(v2.x, v2.y); d[5] = __floats2half2_rn(v2.z, v2.w);
            d[6] = __floats2half2_rn(v3.x, v3.y); d[7] = __floats2half2_rn(v3.z, v3.w);
        }
        __syncthreads();
#pragma unroll
        for (int ks = 0; ks < 32; ks += 16) {
            wmma::fragment<wmma::matrix_a, 16, 16, 16, __half, wmma::row_major> af[2];
            wmma::fragment<wmma::matrix_b, 16, 16, 16, __half, wmma::col_major> bf[4];
#pragma unroll
            for (int i = 0; i < 2; i++)
                wmma::load_matrix_sync(af[i], &sX[warp_m * 32 + i * 16][ks], 40);
#pragma unroll
            for (int j = 0; j < 4; j++)
                wmma::load_matrix_sync(bf[j], &sW[warp_n * 64 + j * 16][ks], 40);
#pragma unroll
            for (int i = 0; i < 2; i++)
#pragma unroll
                for (int j = 0; j < 4; j++)
                    wmma::mma_sync(acc[i][j], af[i], bf[j], acc[i][j]);
        }
        __syncthreads();
    }
    // stage fp32 result to smem
#pragma unroll
    for (int i = 0; i < 2; i++)
#pragma unroll
        for (int j = 0; j < 4; j++)
            wmma::store_matrix_sync(&sH[(size_t)(warp_m * 32 + i * 16) * 128 +
                                        warp_n * 64 + j * 16],
                                    acc[i][j], 128, wmma::mem_row_major);
    __syncthreads();
    // bias + fp16 convert + coalesced store
#pragma unroll
    for (int it = 0; it < 8; it++) {
        int lin = it * 256 + tid;            // 0..2047
        int r = lin >> 4;
        int seg = lin & 15;                  // 8-half segment
        int gr = row0 + r;
        if (gr < nrows) {
            const float* src = &sH[(size_t)r * 128 + seg * 8];
            const float* bb = &sB[seg * 8];
            __half2 h0 = __floats2half2_rn(src[0] + bb[0], src[1] + bb[1]);
            __half2 h1 = __floats2half2_rn(src[2] + bb[2], src[3] + bb[3]);
            __half2 h2 = __floats2half2_rn(src[4] + bb[4], src[5] + bb[5]);
            __half2 h3 = __floats2half2_rn(src[6] + bb[6], src[7] + bb[7]);
            uint4 o;
            o.x = *(unsigned*)&h0; o.y = *(unsigned*)&h1;
            o.z = *(unsigned*)&h2; o.w = *(unsigned*)&h3;
            *(uint4*)&H16[(size_t)gr * C + seg * 8] = o;
        }
    }
}

// ---------------- prep: uw = W^T wsrc / W^T wdst + b dots --------------------
__global__ void prep_uw_kernel(const float* __restrict__ W,
                               const float* __restrict__ b,
                               const float* __restrict__ wsrc,
                               const float* __restrict__ wdst) {
    int k = threadIdx.x;          // 128 threads
    float a = 0.f, c = 0.f;
#pragma unroll 8
    for (int j = 0; j < C; j++) {
        float wj = W[(size_t)j * C + k];
        a = fmaf(wj, wsrc[j], a);
        c = fmaf(wj, wdst[j], c);
    }
    g_uw[k] = a;
    g_uw[C + k] = c;
    if (k == 0) {
        float cs = 0.f, cd = 0.f;
        for (int j = 0; j < C; j++) { cs += b[j] * wsrc[j]; cd += b[j] * wdst[j]; }
        g_uw[2 * C] = cs;
        g_uw[2 * C + 1] = cd;
    }
}

// ---------------- s = X uws + cs, d = X uwd + cd (warp per row) -------------
__global__ void sd_kernel(const float* __restrict__ X,
                          float* __restrict__ s, float* __restrict__ d) {
    int w = (blockIdx.x * blockDim.x + threadIdx.x) >> 5;
    int lane = threadIdx.x & 31;
    if (w >= NV) return;
    float4 h = *(const float4*)&X[(size_t)w * C + lane * 4];
    float4 a = *(const float4*)&g_uw[lane * 4];
    float4 bb = *(const float4*)&g_uw[C + lane * 4];
    float ss = h.x * a.x + h.y * a.y + h.z * a.z + h.w * a.w;
    float dd = h.x * bb.x + h.y * bb.y + h.z * bb.z + h.w * bb.w;
#pragma unroll
    for (int o = 16; o; o >>= 1) {
        ss += __shfl_xor_sync(0xffffffffu, ss, o);
        dd += __shfl_xor_sync(0xffffffffu, dd, o);
    }
    if (lane == 0) { s[w] = ss + g_uw[2 * C]; d[w] = dd + g_uw[2 * C + 1]; }
}

// ---------------- CSR build: histogram -------------------------------------
__global__ void hist_kernel(const int* __restrict__ pv, const int* __restrict__ pe) {
    int p = blockIdx.x * blockDim.x + threadIdx.x;
    if (p >= PP) return;
    atomicAdd(&g_cnt_v[pv[p]], 1);
    atomicAdd(&g_cnt_e[pe[p]], 1);
}

// ---------------- 3-phase exclusive scan ------------------------------------
__global__ void scan_reduce_kernel(const int* __restrict__ in, int* __restrict__ part, int n) {
    __shared__ int wsum[32];
    int i = blockIdx.x * SCAN_B + threadIdx.x;
    int v = (i < n) ? in[i] : 0;
    int lane = threadIdx.x & 31, wid = threadIdx.x >> 5;
#pragma unroll
    for (int o = 16; o; o >>= 1) v += __shfl_xor_sync(0xffffffffu, v, o);
    if (lane == 0) wsum[wid] = v;
    __syncthreads();
    if (wid == 0) {
        int x = (lane < (SCAN_B >> 5)) ? wsum[lane] : 0;
#pragma unroll
        for (int o = 16; o; o >>= 1) x += __shfl_xor_sync(0xffffffffu, x, o);
        if (lane == 0) part[blockIdx.x] = x;
    }
}
__global__ void scan_partials_kernel(int* __restrict__ part, int nb) {
    __shared__ int wsum[32];
    int tid = threadIdx.x, lane = tid & 31, wid = tid >> 5;
    int v = (tid < nb) ? part[tid] : 0;
    int x = v;
#pragma unroll
    for (int o = 1; o < 32; o <<= 1) {
        int t = __shfl_up_sync(0xffffffffu, x, o);
        if (lane >= o) x += t;
    }
    if (lane == 31) wsum[wid] = x;
    __syncthreads();
    if (wid == 0) {
        int w = (lane < 32) ? wsum[lane] : 0;
#pragma unroll
        for (int o = 1; o < 32; o <<= 1) {
            int t = __shfl_up_sync(0xffffffffu, w, o);
            if (lane >= o) w += t;
        }
        wsum[lane] = w;
    }
    __syncthreads();
    int off = (wid == 0) ? 0 : wsum[wid - 1];
    if (tid < nb) part[tid] = off + x - v;     // exclusive
}
__global__ void scan_apply_kernel(const int* __restrict__ in,
                                  const int* __restrict__ part,
                                  int* __restrict__ off, int* __restrict__ cur,
                                  float* __restrict__ invd,
                                  float* __restrict__ disqrt,
                                  int n) {
    __shared__ int wsum[32];
    int i = blockIdx.x * SCAN_B + threadIdx.x;
    int lane = threadIdx.x & 31, wid = threadIdx.x >> 5;
    int v = (i < n) ? in[i] : 0;
    int x = v;
#pragma unroll
    for (int o = 1; o < 32; o <<= 1) {
        int t = __shfl_up_sync(0xffffffffu, x, o);
        if (lane >= o) x += t;
    }
    if (lane == 31) wsum[wid] = x;
    __syncthreads();
    if (wid == 0) {
        int w = (lane < (SCAN_B >> 5)) ? wsum[lane] : 0;
#pragma unroll
        for (int o = 1; o < 32; o <<= 1) {
            int t = __shfl_up_sync(0xffffffffu, w, o);
            if (lane >= o) w += t;
        }
        wsum[lane] = w;
    }
    __syncthreads();
    int woff = (wid == 0) ? 0 : wsum[wid - 1];
    if (i < n) {
        int val = part[blockIdx.x] + woff + x - v;
        off[i] = val;
        cur[i] = val;
        float deg = (float)max(v, 1);
        invd[i] = 1.f / deg;
        if (disqrt) disqrt[i] = rsqrtf(deg);
    }
    if (i == 0) off[n] = PP;
}

// ---------------- CSR fill (packed v-side payload) ---------------------------
__global__ void fill_kernel(const int* __restrict__ pv, const int* __restrict__ pe,
                            const int* __restrict__ sv) {
    int p = blockIdx.x * blockDim.x + threadIdx.x;
    if (p >= PP) return;
    int v = pv[p], e = pe[p];
    int slot_v = atomicAdd(&g_cur_v[v], 1);
    g_csr_v_pack[slot_v] = make_int2(e, sv[p]);
    int slot_e = atomicAdd(&g_cur_e[e], 1);
    g_csr_e_src[slot_e] = v;
}

// ---------------- softmax: warp per vertex, register-cached scores ----------
__device__ __forceinline__ float slot_score(const float* s, int i, float dval) {
    float x = __ldg(&s[g_csr_v_pack[i].y]) + dval;
    x = x > 0.f ? x : NEG_SLOPE * x;
    return fminf(fmaxf(x, 0.001f), 5.0f);
}

__global__ void softmax_kernel(const float* __restrict__ s,
                               const float* __restrict__ d) {
    int v = blockIdx.x * (blockDim.x >> 5) + (threadIdx.x >> 5);
    if (v >= NV) return;
    int lane = threadIdx.x & 31;
    int beg = g_off_v[v], end = g_off_v[v + 1];
    int n = end - beg;
    if (n == 0) return;
    float dval = __ldg(&d[v]);
    if (n <= 128) {
        float sc[4];
        int k = 0;
        float mx = -1e30f;
        for (int i = beg + lane; i < end; i += 32, k++) {
            sc[k] = slot_score(s, i, dval);
            mx = fmaxf(mx, sc[k]);
        }
#pragma unroll
        for (int o = 16; o; o >>= 1) mx = fmaxf(mx, __shfl_xor_sync(0xffffffffu, mx, o));
        float sum = 0.f;
        k = 0;
        for (int i = beg + lane; i < end; i += 32, k++) {
            sc[k] = __expf(sc[k] - mx);
            sum += sc[k];
        }
#pragma unroll
        for (int o = 16; o; o >>= 1) sum += __shfl_xor_sync(0xffffffffu, sum, o);
        float inv = 1.f / sum;
        k = 0;
        for (int i = beg + lane; i < end; i += 32, k++)
            g_alpha[i] = sc[k] * inv;
    } else {
        float mx = -1e30f;
        for (int i = beg + lane; i < end; i += 32) {
            float x = slot_score(s, i, dval);
            g_alpha[i] = x;
            mx = fmaxf(mx, x);
        }
#pragma unroll
        for (int o = 16; o; o >>= 1) mx = fmaxf(mx, __shfl_xor_sync(0xffffffffu, mx, o));
        float sum = 0.f;
        for (int i = beg + lane; i < end; i += 32) {
            float e = __expf(g_alpha[i] - mx);
            g_alpha[i] = e;
            sum += e;
        }
#pragma unroll
        for (int o = 16; o; o >>= 1) sum += __shfl_xor_sync(0xffffffffu, sum, o);
        float inv = 1.f / sum;
        for (int i = beg + lane; i < end; i += 32)
            g_alpha[i] *= inv;
    }
}

// ---------------- CSR gather segment-sum, fp16 rows -------------------------
// warp per output row; half-warp per pair; uint4 (8 halfs) per lane.
// IDX2: csr entries are int2, source index is .x
template<bool IDX2, bool SRC_SCALE, bool PAIRW, bool FINAL>
__global__ void gather_kernel(const __half* __restrict__ src,
                              void* __restrict__ dstv,
                              const void* __restrict__ csrv,
                              const int* __restrict__ off,
                              const float* __restrict__ sscale,
                              const float* __restrict__ pw,
                              const float* __restrict__ oscale,
                              int nrows) {
    int row = blockIdx.x * (blockDim.x >> 5) + (threadIdx.x >> 5);
    if (row >= nrows) return;
    int lane = threadIdx.x & 31;
    int half = lane >> 4;
    int hl = lane & 15;
    int beg = __ldg(&off[row]), end = __ldg(&off[row + 1]);
    const uint4* s4 = (const uint4*)src;
    const int*  csr1 = (const int*)csrv;
    const int2* csr2 = (const int2*)csrv;
    float acc[8];
#pragma unroll
    for (int c = 0; c < 8; c++) acc[c] = 0.f;

    int i = beg;
    for (; i + 8 <= end; i += 8) {
        int idx[4]; float w[4]; uint4 r[4];
#pragma unroll
        for (int u = 0; u < 4; u++)
            idx[u] = IDX2 ? __ldg(&csr2[i + 2 * u + half]).x
                          : __ldg(&csr1[i + 2 * u + half]);
#pragma unroll
        for (int u = 0; u < 4; u++) {
            w[u] = 1.f;
            if (SRC_SCALE) w[u] *= __ldg(&sscale[idx[u]]);
            if (PAIRW)     w[u] *= __ldg(&pw[i + 2 * u + half]);
        }
#pragma unroll
        for (int u = 0; u < 4; u++) r[u] = __ldg(&s4[(size_t)idx[u] * 16 + hl]);
#pragma unroll
        for (int u = 0; u < 4; u++) {
            float2 f0 = __half22float2(*(__half2*)&r[u].x);
            float2 f1 = __half22float2(*(__half2*)&r[u].y);
            float2 f2 = __half22float2(*(__half2*)&r[u].z);
            float2 f3 = __half22float2(*(__half2*)&r[u].w);
            acc[0] = fmaf(w[u], f0.x, acc[0]); acc[1] = fmaf(w[u], f0.y, acc[1]);
            acc[2] = fmaf(w[u], f1.x, acc[2]); acc[3] = fmaf(w[u], f1.y, acc[3]);
            acc[4] = fmaf(w[u], f2.x, acc[4]); acc[5] = fmaf(w[u], f2.y, acc[5]);
            acc[6] = fmaf(w[u], f3.x, acc[6]); acc[7] = fmaf(w[u], f3.y, acc[7]);
        }
    }
    for (; i < end; i += 2) {
        int j = i + half;
        if (j < end) {
            int idx = IDX2 ? __ldg(&csr2[j]).x : __ldg(&csr1[j]);
            float w = 1.f;
            if (SRC_SCALE) w *= __ldg(&sscale[idx]);
            if (PAIRW)     w *= __ldg(&pw[j]);
            uint4 r = __ldg(&s4[(size_t)idx * 16 + hl]);
            float2 f0 = __half22float2(*(__half2*)&r.x);
            float2 f1 = __half22float2(*(__half2*)&r.y);
            float2 f2 = __half22float2(*(__half2*)&r.z);
            float2 f3 = __half22float2(*(__half2*)&r.w);
            acc[0] = fmaf(w, f0.x, acc[0]); acc[1] = fmaf(w, f0.y, acc[1]);
            acc[2] = fmaf(w, f1.x, acc[2]); acc[3] = fmaf(w, f1.y, acc[3]);
            acc[4] = fmaf(w, f2.x, acc[4]); acc[5] = fmaf(w, f2.y, acc[5]);
            acc[6] = fmaf(w, f3.x, acc[6]); acc[7] = fmaf(w, f3.y, acc[7]);
        }
    }
#pragma unroll
    for (int c = 0; c < 8; c++)
        acc[c] += __shfl_xor_sync(0xffffffffu, acc[c], 16);

    float os = oscale ? __ldg(&oscale[row]) : 1.f;
#pragma unroll
    for (int c = 0; c < 8; c++) acc[c] *= os;

    if (lane < 16) {
        if (FINAL) {
#pragma unroll
            for (int c = 0; c < 8; c++)
                acc[c] = acc[c] > 0.f ? acc[c] : expm1f(acc[c]);
            float* o = (float*)dstv + (size_t)row * C + hl * 8;
            *(float4*)o       = make_float4(acc[0], acc[1], acc[2], acc[3]);
            *(float4*)(o + 4) = make_float4(acc[4], acc[5], acc[6], acc[7]);
        } else {
            __half2 h0 = __floats2half2_rn(acc[0], acc[1]);
            __half2 h1 = __floats2half2_rn(acc[2], acc[3]);
            __half2 h2 = __floats2half2_rn(acc[4], acc[5]);
            __half2 h3 = __floats2half2_rn(acc[6], acc[7]);
            uint4 o;
            o.x = *(unsigned*)&h0; o.y = *(unsigned*)&h1;
            o.z = *(unsigned*)&h2; o.w = *(unsigned*)&h3;
            ((uint4*)dstv)[(size_t)row * 16 + hl] = o;
        }
    }
}

// ---------------- launch ------------------------------------------------------
extern "C" void kernel_launch(void* const* d_in, const int* in_sizes, int n_in,
                              void* d_out, int out_size) {
    const float* X      = (const float*)d_in[0];
    const int*   pair_v = (const int*)d_in[1];
    const int*   pair_e = (const int*)d_in[2];
    const int*   src_v  = (const int*)d_in[3];
    const float* Wt     = (const float*)d_in[4];
    const float* bt     = (const float*)d_in[5];
    const float* wsrc   = (const float*)d_in[6];
    const float* wdst   = (const float*)d_in[7];
    float* out = (float*)d_out;

    void *pH16, *pE, *pV, *ps, *pd, *pcv, *pce, *pov, *poe, *pcurv, *pcure;
    void *pdvi, *pinvde, *pinvdv, *palpha, *pcsrvp, *pcsres, *ppartv, *pparte;
    cudaGetSymbolAddress(&pH16, g_H16);
    cudaGetSymbolAddress(&pE,   g_Edge);
    cudaGetSymbolAddress(&pV,   g_Vert);
    cudaGetSymbolAddress(&ps,   g_s);
    cudaGetSymbolAddress(&pd,   g_d);
    cudaGetSymbolAddress(&pcv,  g_cnt_v);
    cudaGetSymbolAddress(&pce,  g_cnt_e);
    cudaGetSymbolAddress(&pov,  g_off_v);
    cudaGetSymbolAddress(&poe,  g_off_e);
    cudaGetSymbolAddress(&pcurv, g_cur_v);
    cudaGetSymbolAddress(&pcure, g_cur_e);
    cudaGetSymbolAddress(&pdvi,   g_dvi);
    cudaGetSymbolAddress(&pinvde, g_inv_de);
    cudaGetSymbolAddress(&pinvdv, g_inv_dv);
    cudaGetSymbolAddress(&palpha, g_alpha);
    cudaGetSymbolAddress(&pcsrvp, g_csr_v_pack);
    cudaGetSymbolAddress(&pcsres, g_csr_e_src);
    cudaGetSymbolAddress(&ppartv, g_part_v);
    cudaGetSymbolAddress(&pparte, g_part_e);

    const __half* H16    = (const __half*)pH16;
    __half*       Ebuf   = (__half*)pE;
    __half*       Vbuf   = (__half*)pV;
    const float*  dvi    = (const float*)pdvi;
    const float*  inv_de = (const float*)pinvde;
    const float*  inv_dv = (const float*)pinvdv;
    const float*  alpha  = (const float*)palpha;
    const int*    off_v  = (const int*)pov;
    const int*    off_e  = (const int*)poe;

    const int TB = 256;
    const int WPB = TB / 32;
    const int pairBlocks = (PP + TB - 1) / TB;
    const int gemmBlocks = (NV + 127) / 128;
    const int eRowBlocks = (ME + WPB - 1) / WPB;
    const int vRowBlocks = (NV + WPB - 1) / WPB;
    const int nbV = (NV + SCAN_B - 1) / SCAN_B;
    const int nbE = (ME + SCAN_B - 1) / SCAN_B;

    // 1) H16 = fp16(X W^T + b) via tensor cores; exact s,d from fp32 X
    cudaFuncSetAttribute(gemm_wmma_kernel,
                         cudaFuncAttributeMaxDynamicSharedMemorySize, 65536);
    gemm_wmma_kernel<<<gemmBlocks, TB, 65536>>>(X, Wt, bt, (__half*)pH16, NV);
    prep_uw_kernel<<<1, C>>>(Wt, bt, wsrc, wdst);
    sd_kernel<<<(NV * 32 + TB - 1) / TB, TB>>>(X, (float*)ps, (float*)pd);

    // 2) CSR build (+ fused degree scales)
    cudaMemsetAsync(pcv, 0, NV * sizeof(int));
    cudaMemsetAsync(pce, 0, ME * sizeof(int));
    hist_kernel<<<pairBlocks, TB>>>(pair_v, pair_e);
    scan_reduce_kernel<<<nbV, SCAN_B>>>((const int*)pcv, (int*)ppartv, NV);
    scan_reduce_kernel<<<nbE, SCAN_B>>>((const int*)pce, (int*)pparte, ME);
    scan_partials_kernel<<<1, SCAN_B>>>((int*)ppartv, nbV);
    scan_partials_kernel<<<1, SCAN_B>>>((int*)pparte, nbE);
    scan_apply_kernel<<<nbV, SCAN_B>>>((const int*)pcv, (const int*)ppartv,
                                       (int*)pov, (int*)pcurv,
                                       (float*)pinvdv, (float*)pdvi, NV);
    scan_apply_kernel<<<nbE, SCAN_B>>>((const int*)pce, (const int*)pparte,
                                       (int*)poe, (int*)pcure,
                                       (float*)pinvde, nullptr, ME);
    fill_kernel<<<pairBlocks, TB>>>(pair_v, pair_e, src_v);

    // 3) softmax alpha (per CSR_v slot)
    softmax_kernel<<<vRowBlocks, TB>>>((const float*)ps, (const float*)pd);

    // 4) feature passes (all gather, no atomics, fp16 rows)
    // P1: Edge = Xe = inv_de * segsum_e( H[v] * dvi[v] )
    gather_kernel<false, true, false, false><<<eRowBlocks, TB>>>(
        H16, Ebuf, pcsres, off_e, dvi, nullptr, inv_de, ME);
    // P2: Vert = Hs = dvi[v] * segsum_v( Edge[e] )
    gather_kernel<true, false, false, false><<<vRowBlocks, TB>>>(
        Ebuf, Vbuf, pcsrvp, off_v, nullptr, nullptr, dvi, NV);
    // P3: Edge = Xe1 = inv_de * segsum_e( Vert[v] )
    gather_kernel<false, false, false, false><<<eRowBlocks, TB>>>(
        Vbuf, Ebuf, pcsres, off_e, nullptr, nullptr, inv_de, ME);
    // P4: Vert = Xv1 = segsum_v( alpha_slot * Edge[e] )
    gather_kernel<true, false, true, false><<<vRowBlocks, TB>>>(
        Ebuf, Vbuf, pcsrvp, off_v, nullptr, alpha, nullptr, NV);
    // P5: Edge = Xe2 = inv_de * segsum_e( Vert[v] )
    gather_kernel<false, false, false, false><<<eRowBlocks, TB>>>(
        Vbuf, Ebuf, pcsres, off_e, nullptr, nullptr, inv_de, ME);
    // P6: out = elu( inv_dv * segsum_v( Edge[e] ) )  (fp32 out)
    gather_kernel<true, false, false, true><<<vRowBlocks, TB>>>(
        Ebuf, out, pcsrvp, off_v, nullptr, nullptr, inv_dv, NV);
}